// round 14
// baseline (speedup 1.0000x reference)
#include <cuda_runtime.h>
#include <cuda_bf16.h>
#include <cstdint>

// Problem constants (fixed shapes)
#define BQ_N 4096
#define NB 4
#define CC 128
#define KN 32
#define R1 5
#define S_TOT (NB * BQ_N)        // 16384 samples
#define S2_TOT (S_TOT * 4)       // 65536 (sample, r) columns
#define CONV_R2 0.04f            // (0.2)^2

// ---------------- scratch (device globals; no allocation allowed) ----------
__device__ uint32_t g_featT[S_TOT * CC];
__device__ uint32_t g_feat0[S_TOT * CC];
__device__ int      g_idx[S_TOT * KN];
__device__ uint32_t g_wf[(size_t)S_TOT * R1 * CC];
__device__ uint32_t g_qf[S_TOT * CC];
__device__ float    g_Y[(size_t)S_TOT * 256];       // fp32 (resid only)
__device__ uint32_t g_h[(size_t)S2_TOT * 256];
// packed weights (N, K) u32
__device__ uint32_t g_wbs[128 * 128];
__device__ uint32_t g_kpTs[128 * 640];
__device__ uint32_t g_wes[128 * 128];
__device__ uint32_t g_w1as[256 * 128];
__device__ uint32_t g_w1cds[256 * 256];
__device__ uint32_t g_m2s[128 * 256];
__device__ float    g_bias2d[4 * 256];

__device__ __forceinline__ uint32_t smem_u32(const void* p) {
    uint32_t a;
    asm("{ .reg .u64 t; cvta.to.shared.u64 t, %1; cvt.u32.u64 %0, t; }"
        : "=r"(a) : "l"(p));
    return a;
}

__device__ __forceinline__ uint32_t bf2_pack(float v0, float v1) {
    __nv_bfloat162 h = __floats2bfloat162_rn(v0, v1);
    return *reinterpret_cast<uint32_t*>(&h);
}
__device__ __forceinline__ float2 bf2_unpack(uint32_t u) {
    __nv_bfloat162 h = *reinterpret_cast<__nv_bfloat162*>(&u);
    return make_float2(__bfloat162float(h.x), __bfloat162float(h.y));
}
__device__ __forceinline__ uint2 pack_hilo(float v0, float v1) {
    uint32_t hi = bf2_pack(v0, v1);
    float2 hf = bf2_unpack(hi);
    uint32_t lo = bf2_pack(v0 - hf.x, v1 - hf.y);
    return make_uint2(hi, lo);
}

#define CP_ASYNC(sa, g) \
    asm volatile("cp.async.cg.shared.global [%0], [%1], 16;" :: "r"(sa), "l"(g) : "memory")
#define CP_COMMIT() asm volatile("cp.async.commit_group;" ::: "memory")
#define CP_WAIT(n)  asm volatile("cp.async.wait_group %0;" :: "n"(n) : "memory")

#define MMA_BF16(d, a0, a1, a2, a3, b0, b1) \
    asm volatile( \
        "mma.sync.aligned.m16n8k16.row.col.f32.bf16.bf16.f32 " \
        "{%0,%1,%2,%3}, {%4,%5,%6,%7}, {%8,%9}, {%0,%1,%2,%3};" \
        : "+f"((d)[0]), "+f"((d)[1]), "+f"((d)[2]), "+f"((d)[3]) \
        : "r"(a0), "r"(a1), "r"(a2), "r"(a3), "r"(b0), "r"(b1))

// bf16x3 triple over a k-step, TERM-MAJOR issue order (groups of 4 ni):
// all lo*hi, then all hi*lo, then all hi*hi -> dependent reuse distance 8
// issues instead of 2, hiding HMMA latency. Per-accumulator term order is
// unchanged (lo*hi, hi*lo, hi*hi) -> numerics identical to the naive order.
#define MMA_BLOCK(ACC, Asb, Bsb, arow, brow, o1, o2, NIv)                     \
    {                                                                          \
        uint2 Af[2][4];                                                        \
        _Pragma("unroll")                                                      \
        for (int mi = 0; mi < 2; mi++) {                                       \
            const uint32_t* p = (Asb) + (((arow) + mi * 16) << 5);             \
            Af[mi][0] = *(const uint2*)(p + (o1));                             \
            Af[mi][1] = *(const uint2*)(p + 256 + (o1));                       \
            Af[mi][2] = *(const uint2*)(p + (o2));                             \
            Af[mi][3] = *(const uint2*)(p + 256 + (o2));                       \
        }                                                                      \
        _Pragma("unroll")                                                      \
        for (int nh = 0; nh < (NIv); nh += 4) {                                \
            uint2 Bf0[4], Bf1[4];                                              \
            _Pragma("unroll")                                                  \
            for (int q = 0; q < 4; q++) {                                      \
                const uint32_t* bp = (Bsb) + (((brow) + (nh + q) * 8) << 5);   \
                Bf0[q] = *(const uint2*)(bp + (o1));                           \
                Bf1[q] = *(const uint2*)(bp + (o2));                           \
            }                                                                  \
            _Pragma("unroll")                                                  \
            for (int q = 0; q < 4; q++)                                        \
                _Pragma("unroll")                                              \
                for (int mi = 0; mi < 2; mi++)                                 \
                    MMA_BF16(ACC[mi][nh + q], Af[mi][0].y, Af[mi][1].y,        \
                             Af[mi][2].y, Af[mi][3].y, Bf0[q].x, Bf1[q].x);    \
            _Pragma("unroll")                                                  \
            for (int q = 0; q < 4; q++)                                        \
                _Pragma("unroll")                                              \
                for (int mi = 0; mi < 2; mi++)                                 \
                    MMA_BF16(ACC[mi][nh + q], Af[mi][0].x, Af[mi][1].x,        \
                             Af[mi][2].x, Af[mi][3].x, Bf0[q].y, Bf1[q].y);    \
            _Pragma("unroll")                                                  \
            for (int q = 0; q < 4; q++)                                        \
                _Pragma("unroll")                                              \
                for (int mi = 0; mi < 2; mi++)                                 \
                    MMA_BF16(ACC[mi][nh + q], Af[mi][0].x, Af[mi][1].x,        \
                             Af[mi][2].x, Af[mi][3].x, Bf0[q].x, Bf1[q].x);    \
        }                                                                      \
    }

// ---------------- bf16x3 mma.sync GEMM, packed hi/lo, hoisted pointers ------
// C[M, 128-tile of Ng] = epi(A @ B^T + bias).
// AMODE 0: row-major (M,K). 1: m -> wf[s=m>>2] slice (m&3)+1 (K=128).
// RESID 0: none; 1: packed bf16 hi/lo; 2: fp32 (RBCAST: row m>>2).
// BMT=64: PAIR mainloop (2 k-tiles per sync). BMT=128: 3-stage, 1 sync/tile.
template <int BMT, int AMODE, bool RELU, int RESID, bool RBCAST, bool BIAS2D,
          bool PERM, bool PACKOUT>
__global__ void __launch_bounds__(256, 2)
mma_gemm(int M, int Ng, int K,
         const uint32_t* __restrict__ A,
         const uint32_t* __restrict__ Bs,
         const float* __restrict__ bias, const void* __restrict__ resid,
         float* __restrict__ C) {
    extern __shared__ uint32_t smu[];
    constexpr int ASIZE = BMT * 32;
    constexpr int SSTRIDE = ASIZE + 4096;
    constexpr int NI = (BMT == 128) ? 8 : 4;
    constexpr int NA = BMT / 32;
    constexpr int NSTG = (BMT == 64) ? 4 : 3;
    int tid = threadIdx.x;
    int lane = tid & 31, wid = tid >> 5;
    int wm = (BMT == 128) ? (wid & 3) : (wid & 1);
    int wn = (BMT == 128) ? (wid >> 2) : (wid >> 1);
    int m0 = blockIdx.y * BMT, n0 = blockIdx.x << 7;
    int nK = K >> 5;
    uint32_t smbase = smem_u32(smu);

    const uint32_t* gA[NA];
    uint32_t saA[NA];
#pragma unroll
    for (int i = 0; i < NA; i++) {
        int c = tid + (i << 8);
        int row = c >> 3, j = c & 7;
        if (AMODE == 0) {
            gA[i] = A + (size_t)(m0 + row) * K + (j << 2);
        } else {
            int m = m0 + row;
            gA[i] = A + (size_t)(m >> 2) * 640 + (((m & 3) + 1) << 7) + (j << 2);
        }
        int ch = j ^ ((row & 3) << 1);
        saA[i] = (row << 5) + (ch << 2);
    }
    const uint32_t* gB[4];
    uint32_t saB[4];
#pragma unroll
    for (int i = 0; i < 4; i++) {
        int c = tid + (i << 8);
        int row = c >> 3, j = c & 7;
        gB[i] = Bs + (size_t)(n0 + row) * K + (j << 2);
        int ch = j ^ ((row & 3) << 1);
        saB[i] = ASIZE + (row << 5) + (ch << 2);
    }

    float acc[2][NI][4];
#pragma unroll
    for (int mi = 0; mi < 2; mi++)
#pragma unroll
        for (int ni = 0; ni < NI; ni++)
#pragma unroll
            for (int u = 0; u < 4; u++) acc[mi][ni][u] = 0.f;

    auto load_tile = [&](int kt) {
        uint32_t st = (kt % NSTG) * SSTRIDE;
#pragma unroll
        for (int i = 0; i < NA; i++) {
            CP_ASYNC(smbase + ((st + saA[i]) << 2), gA[i]);
            gA[i] += 32;
        }
#pragma unroll
        for (int i = 0; i < 4; i++) {
            CP_ASYNC(smbase + ((st + saB[i]) << 2), gB[i]);
            gB[i] += 32;
        }
        CP_COMMIT();
    };

    int g = lane >> 2, kc = lane & 3;
    int swz = (g & 3) << 2;
    int arow = wm * 32 + g;
    int brow = wn * ((BMT == 128) ? 64 : 32) + g;
    int o1v[2], o2v[2];
#pragma unroll
    for (int ks = 0; ks < 2; ks++) {
        o1v[ks] = 2 * ((ks * 8 + kc) ^ swz);
        o2v[ks] = 2 * ((ks * 8 + kc + 4) ^ swz);
    }

    if (BMT == 64) {
        load_tile(0);
        load_tile(1);
        for (int kt = 0; kt < nK; kt += 2) {
            CP_WAIT(0);
            __syncthreads();
            if (kt + 2 < nK) {
                load_tile(kt + 2);
                load_tile(kt + 3);
            }
#pragma unroll
            for (int half = 0; half < 2; half++) {
                const uint32_t* Asb = smu + ((kt + half) % NSTG) * SSTRIDE;
                const uint32_t* Bsb = Asb + ASIZE;
#pragma unroll
                for (int ks = 0; ks < 2; ks++) {
                    MMA_BLOCK(acc, Asb, Bsb, arow, brow, o1v[ks], o2v[ks], NI);
                }
            }
        }
    } else {
        load_tile(0);
        load_tile(1);
        for (int kt = 0; kt < nK; kt++) {
            if (kt + 1 < nK) { CP_WAIT(1); } else { CP_WAIT(0); }
            __syncthreads();
            if (kt + 2 < nK) load_tile(kt + 2);
            const uint32_t* Asb = smu + (kt % NSTG) * SSTRIDE;
            const uint32_t* Bsb = Asb + ASIZE;
#pragma unroll
            for (int ks = 0; ks < 2; ks++) {
                MMA_BLOCK(acc, Asb, Bsb, arow, brow, o1v[ks], o2v[ks], NI);
            }
        }
    }

    // Epilogue. c0:(g,2t) c1:(g,2t+1) c2:(g+8,2t) c3:(g+8,2t+1)
    int mrow = m0 + wm * 32 + g;
    int rsel = mrow & 3;
    int nc0 = n0 + wn * ((BMT == 128) ? 64 : 32) + 2 * kc;
    const uint32_t* Rp = (const uint32_t*)resid;
    const float* Rf = (const float*)resid;
#pragma unroll
    for (int ni = 0; ni < NI; ni++) {
        int n = nc0 + ni * 8;
        int boff = BIAS2D ? rsel * Ng : 0;
        float bv0 = bias[boff + n], bv1 = bias[boff + n + 1];
#pragma unroll
        for (int mi = 0; mi < 2; mi++) {
#pragma unroll
            for (int h2 = 0; h2 < 2; h2++) {
                int m = mrow + mi * 16 + h2 * 8;
                float x0 = acc[mi][ni][2 * h2]     + bv0;
                float x1 = acc[mi][ni][2 * h2 + 1] + bv1;
                if (RESID == 1) {
                    uint2 rv = *(const uint2*)(Rp + (size_t)m * Ng + n);
                    float2 rh = bf2_unpack(rv.x), rl = bf2_unpack(rv.y);
                    x0 += rh.x + rl.x;
                    x1 += rh.y + rl.y;
                } else if (RESID == 2) {
                    size_t rr = RBCAST ? ((size_t)(m >> 2) * Ng + n)
                                       : ((size_t)m * Ng + n);
                    x0 += Rf[rr];
                    x1 += Rf[rr + 1];
                }
                if (RELU) { x0 = fmaxf(x0, 0.f); x1 = fmaxf(x1, 0.f); }
                if (PERM) {
                    int bb = m >> 14;
                    size_t low = (size_t)(m & 16383);
                    C[(((size_t)(bb * 128 + n)) << 14) + low] = x0;
                    C[(((size_t)(bb * 128 + n + 1)) << 14) + low] = x1;
                } else if (PACKOUT) {
                    uint2 pw = pack_hilo(x0, x1);
                    *(uint2*)((uint32_t*)C + (size_t)m * Ng + n) = pw;
                } else {
                    *(float2*)(C + (size_t)m * Ng + n) = make_float2(x0, x1);
                }
            }
        }
    }
}

// ---------------- fused qf2 + Y kernel (BM=64) ------------------------------
__global__ void __launch_bounds__(256, 2)
fused_qf2_y(const uint32_t* __restrict__ qf, const uint32_t* __restrict__ wes,
            const float* __restrict__ b_end, const uint32_t* __restrict__ featT,
            const uint32_t* __restrict__ w1cds, const float* __restrict__ b_mlp1,
            float* __restrict__ Y) {
    extern __shared__ uint32_t smu[];
    uint32_t* Hs = smu;                     // 4 tiles x 2048 u32 = 8192
    const uint32_t PIPE = 8192;             // 3 stages x (A 2048 + B 4096)
    const int SSTRIDE = 6144;
    int tid = threadIdx.x;
    int lane = tid & 31, wid = tid >> 5;
    int wm = wid & 1, wn = wid >> 1;
    int m0 = blockIdx.x << 6;
    uint32_t smbase = smem_u32(smu);

    int g = lane >> 2, kc = lane & 3;
    int swz = (g & 3) << 2;
    int arow = wm * 32 + g;
    int brow = wn * 32 + g;
    int o1v[2], o2v[2];
#pragma unroll
    for (int ks = 0; ks < 2; ks++) {
        o1v[ks] = 2 * ((ks * 8 + kc) ^ swz);
        o2v[ks] = 2 * ((ks * 8 + kc + 4) ^ swz);
    }

    int rowA[2], jA[2];
    uint32_t saA[2];
#pragma unroll
    for (int i = 0; i < 2; i++) {
        int c = tid + (i << 8);
        int row = c >> 3, j = c & 7;
        rowA[i] = row; jA[i] = j;
        int ch = j ^ ((row & 3) << 1);
        saA[i] = (row << 5) + (ch << 2);
    }
    int rowB[4], jB[4];
    uint32_t saB[4];
#pragma unroll
    for (int i = 0; i < 4; i++) {
        int c = tid + (i << 8);
        int row = c >> 3, j = c & 7;
        rowB[i] = row; jB[i] = j;
        int ch = j ^ ((row & 3) << 1);
        saB[i] = 2048 + (row << 5) + (ch << 2);
    }

    // ===== Phase 1: qf2 tile (K=128, 4 k-tiles, 3-stage) =====
    {
        auto load1 = [&](int kt) {
            uint32_t st = PIPE + (kt % 3) * SSTRIDE;
#pragma unroll
            for (int i = 0; i < 2; i++)
                CP_ASYNC(smbase + ((st + saA[i]) << 2),
                         qf + (size_t)(m0 + rowA[i]) * 128 + (kt << 5) + (jA[i] << 2));
#pragma unroll
            for (int i = 0; i < 4; i++)
                CP_ASYNC(smbase + ((st + saB[i]) << 2),
                         wes + (size_t)rowB[i] * 128 + (kt << 5) + (jB[i] << 2));
            CP_COMMIT();
        };
        load1(0);
        load1(1);
        float acc[2][4][4];
#pragma unroll
        for (int mi = 0; mi < 2; mi++)
#pragma unroll
            for (int ni = 0; ni < 4; ni++)
#pragma unroll
                for (int u = 0; u < 4; u++) acc[mi][ni][u] = 0.f;
        for (int kt = 0; kt < 4; kt++) {
            if (kt < 3) { CP_WAIT(1); } else { CP_WAIT(0); }
            __syncthreads();
            if (kt + 2 < 4) load1(kt + 2);
            const uint32_t* Asb = smu + PIPE + (kt % 3) * SSTRIDE;
            const uint32_t* Bsb = Asb + 2048;
#pragma unroll
            for (int ks = 0; ks < 2; ks++) {
                MMA_BLOCK(acc, Asb, Bsb, arow, brow, o1v[ks], o2v[ks], 4);
            }
        }
        int nc0 = wn * 32 + 2 * kc;
#pragma unroll
        for (int ni = 0; ni < 4; ni++) {
            int n = nc0 + ni * 8;
            float bv0 = b_end[n], bv1 = b_end[n + 1];
#pragma unroll
            for (int mi = 0; mi < 2; mi++) {
#pragma unroll
                for (int h2 = 0; h2 < 2; h2++) {
                    int ml = arow + mi * 16 + h2 * 8;
                    uint2 rv = *(const uint2*)(featT + ((size_t)(m0 + ml) << 7) + n);
                    float2 rh = bf2_unpack(rv.x), rl = bf2_unpack(rv.y);
                    float x0 = acc[mi][ni][2 * h2]     + bv0 + rh.x + rl.x;
                    float x1 = acc[mi][ni][2 * h2 + 1] + bv1 + rh.y + rl.y;
                    x0 = fmaxf(x0, 0.f);
                    x1 = fmaxf(x1, 0.f);
                    uint2 pw = pack_hilo(x0, x1);
                    int p = n >> 1;
                    uint32_t off = (uint32_t)(p >> 4) * 2048 + (ml << 5)
                                 + 2 * ((p & 15) ^ ((ml & 3) << 2));
                    *(uint2*)(Hs + off) = pw;
                }
            }
        }
    }

    // ===== Phase 2: Y, two n-passes, K=256 (kt<4 from Hs, kt>=4 featT) =====
#pragma unroll 1
    for (int np = 0; np < 2; np++) {
        __syncthreads();
        const uint32_t* Bb = w1cds + ((size_t)np << 15);
        auto load2 = [&](int kt) {
            uint32_t st = PIPE + (kt % 3) * SSTRIDE;
            if (kt >= 4) {
#pragma unroll
                for (int i = 0; i < 2; i++)
                    CP_ASYNC(smbase + ((st + saA[i]) << 2),
                             featT + ((size_t)(m0 + rowA[i]) << 7) + ((kt - 4) << 5) + (jA[i] << 2));
            }
#pragma unroll
            for (int i = 0; i < 4; i++)
                CP_ASYNC(smbase + ((st + saB[i]) << 2),
                         Bb + (size_t)rowB[i] * 256 + (kt << 5) + (jB[i] << 2));
            CP_COMMIT();
        };
        load2(0);
        load2(1);
        float acc[2][4][4];
#pragma unroll
        for (int mi = 0; mi < 2; mi++)
#pragma unroll
            for (int ni = 0; ni < 4; ni++)
#pragma unroll
                for (int u = 0; u < 4; u++) acc[mi][ni][u] = 0.f;
        for (int kt = 0; kt < 8; kt++) {
            if (kt < 7) { CP_WAIT(1); } else { CP_WAIT(0); }
            __syncthreads();
            if (kt + 2 < 8) load2(kt + 2);
            const uint32_t* slot = smu + PIPE + (kt % 3) * SSTRIDE;
            const uint32_t* Asb = (kt < 4) ? (Hs + kt * 2048) : slot;
            const uint32_t* Bsb = slot + 2048;
#pragma unroll
            for (int ks = 0; ks < 2; ks++) {
                MMA_BLOCK(acc, Asb, Bsb, arow, brow, o1v[ks], o2v[ks], 4);
            }
        }
        int nc0 = (np << 7) + wn * 32 + 2 * kc;
#pragma unroll
        for (int ni = 0; ni < 4; ni++) {
            int n = nc0 + ni * 8;
            float bv0 = b_mlp1[n], bv1 = b_mlp1[n + 1];
#pragma unroll
            for (int mi = 0; mi < 2; mi++) {
#pragma unroll
                for (int h2 = 0; h2 < 2; h2++) {
                    int m = m0 + arow + mi * 16 + h2 * 8;
                    float x0 = acc[mi][ni][2 * h2]     + bv0;
                    float x1 = acc[mi][ni][2 * h2 + 1] + bv1;
                    *(float2*)(Y + ((size_t)m << 8) + n) = make_float2(x0, x1);
                }
            }
        }
    }
}

// -------- kernel-point correlation: packed feat0 -> packed wf --------------
__global__ void kp_wf_kernel(const float* __restrict__ pos,
                             const int* __restrict__ idx,
                             const float* __restrict__ qp,
                             const uint32_t* __restrict__ feat0,
                             uint32_t* __restrict__ wf) {
    int s = blockIdx.x;
    int b = s >> 12, n = s & (BQ_N - 1);
    int c = threadIdx.x;
    __shared__ float wsh[R1][KN];
    __shared__ int nidx[KN];
    if (c < KN) {
        int m = idx[(size_t)s * KN + c];
        nidx[c] = m;
        float wr[R1];
#pragma unroll
        for (int r = 0; r < R1; r++) wr[r] = 0.f;
        if (m < BQ_N) {
            const float* p = pos + (size_t)b * 3 * BQ_N;
            float rx = p[m] - p[n];
            float ry = p[BQ_N + m] - p[BQ_N + n];
            float rz = p[2 * BQ_N + m] - p[2 * BQ_N + n];
#pragma unroll
            for (int r = 0; r < R1; r++) {
                float dx = rx - qp[r];
                float dy = ry - qp[R1 + r];
                float dz = rz - qp[2 * R1 + r];
                float d = sqrtf(dx * dx + dy * dy + dz * dz);
                wr[r] = fmaxf(0.f, 1.f - d / 0.1f);
            }
        }
#pragma unroll
        for (int r = 0; r < R1; r++) wsh[r][c] = wr[r];
    }
    __syncthreads();
    float acc[R1] = {0.f, 0.f, 0.f, 0.f, 0.f};
    bool odd = (c & 1);
    int ce = c & ~1;
#pragma unroll 4
    for (int k = 0; k < KN; k++) {
        int m = nidx[k];
        float f = 0.f;
        if (m < BQ_N) {
            uint2 w = *(const uint2*)(feat0 + (((size_t)(b * BQ_N + m)) << 7) + ce);
            float2 hh = bf2_unpack(w.x), ll = bf2_unpack(w.y);
            f = odd ? (hh.y + ll.y) : (hh.x + ll.x);
        }
#pragma unroll
        for (int r = 0; r < R1; r++) acc[r] += wsh[r][k] * f;
    }
#pragma unroll
    for (int r = 0; r < R1; r++) {
        float v = acc[r];
        float vp = __shfl_xor_sync(0xffffffffu, v, 1);
        if (!odd) {
            uint2 pw = pack_hilo(v, vp);
            *(uint2*)(wf + (size_t)s * 640 + r * 128 + c) = pw;
        }
    }
}

// ---- setup: transpose(+pack) | ballquery | prep, by blockIdx range --------
#define T_BLOCKS 2048
#define B_BLOCKS 2048         // 1 point per warp, direct LDG
#define PREP_TOTAL (8192 + 40960 + 8192 + 16384 + 32768 + 16384 + 1024 + 12)
#define P_BLOCKS ((PREP_TOTAL + 255) / 256)

__global__ void __launch_bounds__(256) setup_kernel(
    const float* __restrict__ feat, const float* __restrict__ pos,
    const float* __restrict__ w_begin, const float* __restrict__ kpw,
    const float* __restrict__ w_end, const float* __restrict__ w1,
    const float* __restrict__ w2, const float* __restrict__ qp,
    uint32_t* __restrict__ featT, int* __restrict__ idx,
    uint32_t* __restrict__ wbs, uint32_t* __restrict__ kpTs,
    uint32_t* __restrict__ wes, uint32_t* __restrict__ w1as,
    uint32_t* __restrict__ w1cds, uint32_t* __restrict__ m2s,
    float* __restrict__ bias2d, float* __restrict__ out12) {
    extern __shared__ float dynf[];
    int bid = blockIdx.x;
    int tid = threadIdx.x;
    if (bid < T_BLOCKS) {
        float (*tile)[33] = (float (*)[33])dynf;
        int b = bid >> 9;
        int n0 = (bid & 127) * 32, c0 = ((bid >> 7) & 3) * 32;
        int tx = tid & 31, ty = tid >> 5;
#pragma unroll
        for (int i = ty; i < 32; i += 8)
            tile[i][tx] = feat[((size_t)(b * CC + c0 + i)) * BQ_N + n0 + tx];
        __syncthreads();
#pragma unroll
        for (int i = ty; i < 32; i += 8) {
            float v = tile[tx][i];
            float vp = __shfl_xor_sync(0xffffffffu, v, 1);
            if (!(tx & 1)) {
                uint2 pw = pack_hilo(v, vp);
                *(uint2*)(featT + (((size_t)(b * BQ_N + n0 + i)) << 7) + c0 + tx) = pw;
            }
        }
        return;
    }
    if (bid < T_BLOCKS + B_BLOCKS) {
        int t = bid - T_BLOCKS;
        int b = t >> 9, bx = t & 511;
        const float* px = pos + (size_t)b * 3 * BQ_N;
        const float* py = px + BQ_N;
        const float* pz = px + 2 * BQ_N;
        int warp = tid >> 5, lane = tid & 31;
        int n = bx * 8 + warp;
        float xn = px[n], yn = py[n], zn = pz[n];
        float nn = xn * xn + yn * yn + zn * zn;
        int* out = idx + (size_t)(b * BQ_N + n) * KN;
        int count = 0;
        for (int m0 = 0; m0 < BQ_N && count < KN; m0 += 32) {
            int m = m0 + lane;
            float xm = px[m], ym = py[m], zm = pz[m];
            float nm = xm * xm + ym * ym + zm * zm;
            float dt = xn * xm + yn * ym + zn * zm;
            float sqd = (nn + nm) - 2.0f * dt;
            bool ok = (sqd <= CONV_R2);
            unsigned msk = __ballot_sync(0xffffffffu, ok);
            int p2 = count + __popc(msk & ((1u << lane) - 1u));
            if (ok && p2 < KN) out[p2] = m;
            count += __popc(msk);
            if (count > KN) count = KN;
        }
        for (int p2 = count + lane; p2 < KN; p2 += 32) out[p2] = BQ_N;
        return;
    }
    int t = (bid - T_BLOCKS - B_BLOCKS) * 256 + tid;
    if (t < 8192) {
        int o = t >> 6, p = t & 63;
        *(uint2*)(wbs + o * 128 + 2 * p) =
            pack_hilo(w_begin[o * 128 + 2 * p], w_begin[o * 128 + 2 * p + 1]);
        return;
    }
    t -= 8192;
    if (t < 40960) {
        int c = t / 320, p = t % 320;
        *(uint2*)(kpTs + (size_t)c * 640 + 2 * p) =
            pack_hilo(kpw[(size_t)(2 * p) * 128 + c], kpw[(size_t)(2 * p + 1) * 128 + c]);
        return;
    }
    t -= 40960;
    if (t < 8192) {
        int o = t >> 6, p = t & 63;
        *(uint2*)(wes + o * 128 + 2 * p) =
            pack_hilo(w_end[o * 128 + 2 * p], w_end[o * 128 + 2 * p + 1]);
        return;
    }
    t -= 8192;
    if (t < 16384) {
        int o = t >> 6, p = t & 63;
        *(uint2*)(w1as + o * 128 + 2 * p) =
            pack_hilo(w1[(size_t)o * 387 + 2 * p], w1[(size_t)o * 387 + 2 * p + 1]);
        return;
    }
    t -= 16384;
    if (t < 32768) {
        int o = t >> 7, p = t & 127;
        *(uint2*)(w1cds + (size_t)o * 256 + 2 * p) =
            pack_hilo(w1[(size_t)o * 387 + 131 + 2 * p], w1[(size_t)o * 387 + 132 + 2 * p]);
        return;
    }
    t -= 32768;
    if (t < 16384) {
        int o = t >> 7, p = t & 127;
        *(uint2*)(m2s + (size_t)o * 256 + 2 * p) =
            pack_hilo(w2[(size_t)o * 256 + 2 * p], w2[(size_t)o * 256 + 2 * p + 1]);
        return;
    }
    t -= 16384;
    if (t < 1024) {
        int r = t >> 8, n = t & 255;
        float s = 0.f;
#pragma unroll
        for (int a = 0; a < 3; a++)
            s += w1[(size_t)n * 387 + 128 + a] * qp[a * R1 + r + 1];
        bias2d[r * 256 + n] = s;
        return;
    }
    t -= 1024;
    if (t >= 0 && t < 12) {
        int a = t >> 2, r = (t & 3) + 1;
        out12[t] = qp[a * R1 + r];
    }
}

// ---------------- launch ----------------------------------------------------
extern "C" void kernel_launch(void* const* d_in, const int* in_sizes, int n_in,
                              void* d_out, int out_size) {
    (void)in_sizes; (void)n_in; (void)out_size;
    const float* pos       = (const float*)d_in[0];
    const float* feat      = (const float*)d_in[1];
    const float* qp        = (const float*)d_in[2];
    const float* w_begin   = (const float*)d_in[3];
    const float* b_begin   = (const float*)d_in[4];
    const float* kp_weight = (const float*)d_in[5];
    const float* kp_bias   = (const float*)d_in[6];
    const float* w_end     = (const float*)d_in[7];
    const float* b_end     = (const float*)d_in[8];
    const float* w_mlp1    = (const float*)d_in[9];
    const float* b_mlp1    = (const float*)d_in[10];
    const float* w_mlp2    = (const float*)d_in[11];
    const float* b_mlp2    = (const float*)d_in[12];
    float* out = (float*)d_out;

    uint32_t *featT, *feat0, *wf, *qf, *h;
    uint32_t *wbs, *kpTs, *wes, *w1as, *w1cds, *m2s;
    float *Y, *bias2d;
    int* idx;
    cudaGetSymbolAddress((void**)&featT, g_featT);
    cudaGetSymbolAddress((void**)&feat0, g_feat0);
    cudaGetSymbolAddress((void**)&idx,   g_idx);
    cudaGetSymbolAddress((void**)&wf,    g_wf);
    cudaGetSymbolAddress((void**)&qf,    g_qf);
    cudaGetSymbolAddress((void**)&Y,     g_Y);
    cudaGetSymbolAddress((void**)&h,     g_h);
    cudaGetSymbolAddress((void**)&wbs,   g_wbs);
    cudaGetSymbolAddress((void**)&kpTs,  g_kpTs);
    cudaGetSymbolAddress((void**)&wes,   g_wes);
    cudaGetSymbolAddress((void**)&w1as,  g_w1as);
    cudaGetSymbolAddress((void**)&w1cds, g_w1cds);
    cudaGetSymbolAddress((void**)&m2s,   g_m2s);
    cudaGetSymbolAddress((void**)&bias2d, g_bias2d);

    const int SMEM_SETUP = 32 * 33 * 4 + 256;
    const int SMEM_S = 4 * (64 * 32 + 4096) * 4;    // 98304 B
    const int SMEM_B = 3 * (128 * 32 + 4096) * 4;   // 98304 B
    const int SMEM_F = (8192 + 3 * 6144) * 4;       // 106496 B
    cudaFuncSetAttribute(setup_kernel,
                         cudaFuncAttributeMaxDynamicSharedMemorySize, SMEM_SETUP);
    cudaFuncSetAttribute(fused_qf2_y,
                         cudaFuncAttributeMaxDynamicSharedMemorySize, SMEM_F);
#define SETSM(SM, ...) cudaFuncSetAttribute(mma_gemm<__VA_ARGS__>, \
        cudaFuncAttributeMaxDynamicSharedMemorySize, SM)
    SETSM(SMEM_S, 64,  0, false, 0, false, false, false, true);
    SETSM(SMEM_S, 64,  0, true,  0, false, false, false, true);
    SETSM(SMEM_B, 128, 1, true,  2, true,  true,  false, true);
    SETSM(SMEM_B, 128, 0, true,  0, false, false, true,  false);
#undef SETSM

    // Stage 0: fused transpose + ball query + prep
    setup_kernel<<<T_BLOCKS + B_BLOCKS + P_BLOCKS, 256, SMEM_SETUP>>>(
        feat, pos, w_begin, kp_weight, w_end, w_mlp1, w_mlp2, qp,
        featT, idx, wbs, kpTs, wes, w1as, w1cds, m2s, bias2d, out);

    // feat0 = featT @ w_begin^T + b_begin          (packed out)
    mma_gemm<64, 0, false, 0, false, false, false, true><<<dim3(1, 256), 256, SMEM_S>>>(
        S_TOT, 128, 128, featT, wbs, b_begin, nullptr, (float*)feat0);

    // kernel-point correlation -> wf (S, 640)      (packed out)
    kp_wf_kernel<<<S_TOT, 128>>>(pos, idx, qp, feat0, wf);

    // qf = relu(wf @ kpT^T + kp_bias)              (packed out)
    mma_gemm<64, 0, true, 0, false, false, false, true><<<dim3(1, 256), 256, SMEM_S>>>(
        S_TOT, 128, 640, wf, kpTs, kp_bias, nullptr, (float*)qf);

    // fused: qf2 (smem only) -> Y = [qf2|featT] @ w1cd^T + b_mlp1
    fused_qf2_y<<<256, 256, SMEM_F>>>(qf, wes, b_end, featT, w1cds, b_mlp1, Y);

    // h = relu(wf_r @ w1a^T + bias2d[r] + Y[s])    (packed out)
    mma_gemm<128, 1, true, 2, true, true, false, true><<<dim3(2, 512), 256, SMEM_B>>>(
        S2_TOT, 256, 128, wf, w1as, bias2d, Y, (float*)h);

    // queries = relu(h @ w_mlp2^T + b_mlp2), scattered to (B, TD, N, R)
    mma_gemm<128, 0, true, 0, false, false, true, false><<<dim3(1, 512), 256, SMEM_B>>>(
        S2_TOT, 128, 256, h, m2s, b_mlp2, nullptr, out + 12);
}

// round 15
// speedup vs baseline: 1.0266x; 1.0266x over previous
#include <cuda_runtime.h>
#include <cuda_bf16.h>
#include <cstdint>

// Problem constants (fixed shapes)
#define BQ_N 4096
#define NB 4
#define CC 128
#define KN 32
#define R1 5
#define S_TOT (NB * BQ_N)        // 16384 samples
#define S2_TOT (S_TOT * 4)       // 65536 (sample, r) columns
#define CONV_R2 0.04f            // (0.2)^2

// ---------------- scratch (device globals; no allocation allowed) ----------
__device__ uint32_t g_featT[S_TOT * CC];
__device__ uint32_t g_feat0[S_TOT * CC];
__device__ int      g_idx[S_TOT * KN];
__device__ uint32_t g_wf[(size_t)S_TOT * R1 * CC];
__device__ uint32_t g_qf[S_TOT * CC];
__device__ float    g_Y[(size_t)S_TOT * 256];       // fp32 (resid only)
__device__ uint32_t g_h[(size_t)S2_TOT * 256];
// packed weights (N, K) u32
__device__ uint32_t g_wbs[128 * 128];
__device__ uint32_t g_kpTs[128 * 640];
__device__ uint32_t g_wes[128 * 128];
__device__ uint32_t g_w1as[256 * 128];
__device__ uint32_t g_w1cds[256 * 256];
__device__ uint32_t g_m2s[128 * 256];
__device__ float    g_bias2d[4 * 256];

__device__ __forceinline__ uint32_t smem_u32(const void* p) {
    uint32_t a;
    asm("{ .reg .u64 t; cvta.to.shared.u64 t, %1; cvt.u32.u64 %0, t; }"
        : "=r"(a) : "l"(p));
    return a;
}

__device__ __forceinline__ uint32_t bf2_pack(float v0, float v1) {
    __nv_bfloat162 h = __floats2bfloat162_rn(v0, v1);
    return *reinterpret_cast<uint32_t*>(&h);
}
__device__ __forceinline__ float2 bf2_unpack(uint32_t u) {
    __nv_bfloat162 h = *reinterpret_cast<__nv_bfloat162*>(&u);
    return make_float2(__bfloat162float(h.x), __bfloat162float(h.y));
}
__device__ __forceinline__ uint2 pack_hilo(float v0, float v1) {
    uint32_t hi = bf2_pack(v0, v1);
    float2 hf = bf2_unpack(hi);
    uint32_t lo = bf2_pack(v0 - hf.x, v1 - hf.y);
    return make_uint2(hi, lo);
}

#define CP_ASYNC(sa, g) \
    asm volatile("cp.async.cg.shared.global [%0], [%1], 16;" :: "r"(sa), "l"(g) : "memory")
#define CP_COMMIT() asm volatile("cp.async.commit_group;" ::: "memory")
#define CP_WAIT(n)  asm volatile("cp.async.wait_group %0;" :: "n"(n) : "memory")

#define MMA_BF16(d, a0, a1, a2, a3, b0, b1) \
    asm volatile( \
        "mma.sync.aligned.m16n8k16.row.col.f32.bf16.bf16.f32 " \
        "{%0,%1,%2,%3}, {%4,%5,%6,%7}, {%8,%9}, {%0,%1,%2,%3};" \
        : "+f"((d)[0]), "+f"((d)[1]), "+f"((d)[2]), "+f"((d)[3]) \
        : "r"(a0), "r"(a1), "r"(a2), "r"(a3), "r"(b0), "r"(b1))

// TERM-MAJOR order (NI=4 kernels): all lo*hi, all hi*lo, all hi*hi across
// the 8 (ni x mi) accumulators -> dependent reuse distance 8 issues.
// Measured better at NI=4 (low reg pressure).
#define MMA_BLOCK_TM(ACC, Asb, Bsb, arow, brow, o1, o2)                       \
    {                                                                          \
        uint2 Af[2][4];                                                        \
        _Pragma("unroll")                                                      \
        for (int mi = 0; mi < 2; mi++) {                                       \
            const uint32_t* p = (Asb) + (((arow) + mi * 16) << 5);             \
            Af[mi][0] = *(const uint2*)(p + (o1));                             \
            Af[mi][1] = *(const uint2*)(p + 256 + (o1));                       \
            Af[mi][2] = *(const uint2*)(p + (o2));                             \
            Af[mi][3] = *(const uint2*)(p + 256 + (o2));                       \
        }                                                                      \
        uint2 Bf0[4], Bf1[4];                                                  \
        _Pragma("unroll")                                                      \
        for (int q = 0; q < 4; q++) {                                          \
            const uint32_t* bp = (Bsb) + (((brow) + q * 8) << 5);              \
            Bf0[q] = *(const uint2*)(bp + (o1));                               \
            Bf1[q] = *(const uint2*)(bp + (o2));                               \
        }                                                                      \
        _Pragma("unroll")                                                      \
        for (int q = 0; q < 4; q++)                                            \
            _Pragma("unroll")                                                  \
            for (int mi = 0; mi < 2; mi++)                                     \
                MMA_BF16(ACC[mi][q], Af[mi][0].y, Af[mi][1].y,                 \
                         Af[mi][2].y, Af[mi][3].y, Bf0[q].x, Bf1[q].x);        \
        _Pragma("unroll")                                                      \
        for (int q = 0; q < 4; q++)                                            \
            _Pragma("unroll")                                                  \
            for (int mi = 0; mi < 2; mi++)                                     \
                MMA_BF16(ACC[mi][q], Af[mi][0].x, Af[mi][1].x,                 \
                         Af[mi][2].x, Af[mi][3].x, Bf0[q].y, Bf1[q].y);        \
        _Pragma("unroll")                                                      \
        for (int q = 0; q < 4; q++)                                            \
            _Pragma("unroll")                                                  \
            for (int mi = 0; mi < 2; mi++)                                     \
                MMA_BF16(ACC[mi][q], Af[mi][0].x, Af[mi][1].x,                 \
                         Af[mi][2].x, Af[mi][3].x, Bf0[q].x, Bf1[q].x);        \
    }

// INTERLEAVED order (NI=8 kernels): per-accumulator triple back-to-back.
// Lower register pressure; measured better at NI=8 (BMT=128).
#define MMA_BLOCK_ILV(ACC, Asb, Bsb, arow, brow, o1, o2, NIv)                 \
    {                                                                          \
        uint2 Af[2][4];                                                        \
        _Pragma("unroll")                                                      \
        for (int mi = 0; mi < 2; mi++) {                                       \
            const uint32_t* p = (Asb) + (((arow) + mi * 16) << 5);             \
            Af[mi][0] = *(const uint2*)(p + (o1));                             \
            Af[mi][1] = *(const uint2*)(p + 256 + (o1));                       \
            Af[mi][2] = *(const uint2*)(p + (o2));                             \
            Af[mi][3] = *(const uint2*)(p + 256 + (o2));                       \
        }                                                                      \
        _Pragma("unroll")                                                      \
        for (int ni = 0; ni < (NIv); ni++) {                                   \
            const uint32_t* bp = (Bsb) + (((brow) + ni * 8) << 5);             \
            uint2 B0 = *(const uint2*)(bp + (o1));                             \
            uint2 B1 = *(const uint2*)(bp + (o2));                             \
            _Pragma("unroll")                                                  \
            for (int mi = 0; mi < 2; mi++) {                                   \
                MMA_BF16(ACC[mi][ni], Af[mi][0].y, Af[mi][1].y, Af[mi][2].y,   \
                         Af[mi][3].y, B0.x, B1.x);                             \
                MMA_BF16(ACC[mi][ni], Af[mi][0].x, Af[mi][1].x, Af[mi][2].x,   \
                         Af[mi][3].x, B0.y, B1.y);                             \
                MMA_BF16(ACC[mi][ni], Af[mi][0].x, Af[mi][1].x, Af[mi][2].x,   \
                         Af[mi][3].x, B0.x, B1.x);                             \
            }                                                                  \
        }                                                                      \
    }

// ---------------- bf16x3 mma.sync GEMM, packed hi/lo, hoisted pointers ------
// C[M, 128-tile of Ng] = epi(A @ B^T + bias).
// AMODE 0: row-major (M,K). 1: m -> wf[s=m>>2] slice (m&3)+1 (K=128).
// RESID 0: none; 1: packed bf16 hi/lo; 2: fp32 (RBCAST: row m>>2).
// BMT=64: PAIR mainloop, TERM-MAJOR mma. BMT=128: 3-stage, INTERLEAVED mma.
template <int BMT, int AMODE, bool RELU, int RESID, bool RBCAST, bool BIAS2D,
          bool PERM, bool PACKOUT>
__global__ void __launch_bounds__(256, 2)
mma_gemm(int M, int Ng, int K,
         const uint32_t* __restrict__ A,
         const uint32_t* __restrict__ Bs,
         const float* __restrict__ bias, const void* __restrict__ resid,
         float* __restrict__ C) {
    extern __shared__ uint32_t smu[];
    constexpr int ASIZE = BMT * 32;
    constexpr int SSTRIDE = ASIZE + 4096;
    constexpr int NI = (BMT == 128) ? 8 : 4;
    constexpr int NA = BMT / 32;
    constexpr int NSTG = (BMT == 64) ? 4 : 3;
    int tid = threadIdx.x;
    int lane = tid & 31, wid = tid >> 5;
    int wm = (BMT == 128) ? (wid & 3) : (wid & 1);
    int wn = (BMT == 128) ? (wid >> 2) : (wid >> 1);
    int m0 = blockIdx.y * BMT, n0 = blockIdx.x << 7;
    int nK = K >> 5;
    uint32_t smbase = smem_u32(smu);

    const uint32_t* gA[NA];
    uint32_t saA[NA];
#pragma unroll
    for (int i = 0; i < NA; i++) {
        int c = tid + (i << 8);
        int row = c >> 3, j = c & 7;
        if (AMODE == 0) {
            gA[i] = A + (size_t)(m0 + row) * K + (j << 2);
        } else {
            int m = m0 + row;
            gA[i] = A + (size_t)(m >> 2) * 640 + (((m & 3) + 1) << 7) + (j << 2);
        }
        int ch = j ^ ((row & 3) << 1);
        saA[i] = (row << 5) + (ch << 2);
    }
    const uint32_t* gB[4];
    uint32_t saB[4];
#pragma unroll
    for (int i = 0; i < 4; i++) {
        int c = tid + (i << 8);
        int row = c >> 3, j = c & 7;
        gB[i] = Bs + (size_t)(n0 + row) * K + (j << 2);
        int ch = j ^ ((row & 3) << 1);
        saB[i] = ASIZE + (row << 5) + (ch << 2);
    }

    float acc[2][NI][4];
#pragma unroll
    for (int mi = 0; mi < 2; mi++)
#pragma unroll
        for (int ni = 0; ni < NI; ni++)
#pragma unroll
            for (int u = 0; u < 4; u++) acc[mi][ni][u] = 0.f;

    auto load_tile = [&](int kt) {
        uint32_t st = (kt % NSTG) * SSTRIDE;
#pragma unroll
        for (int i = 0; i < NA; i++) {
            CP_ASYNC(smbase + ((st + saA[i]) << 2), gA[i]);
            gA[i] += 32;
        }
#pragma unroll
        for (int i = 0; i < 4; i++) {
            CP_ASYNC(smbase + ((st + saB[i]) << 2), gB[i]);
            gB[i] += 32;
        }
        CP_COMMIT();
    };

    int g = lane >> 2, kc = lane & 3;
    int swz = (g & 3) << 2;
    int arow = wm * 32 + g;
    int brow = wn * ((BMT == 128) ? 64 : 32) + g;
    int o1v[2], o2v[2];
#pragma unroll
    for (int ks = 0; ks < 2; ks++) {
        o1v[ks] = 2 * ((ks * 8 + kc) ^ swz);
        o2v[ks] = 2 * ((ks * 8 + kc + 4) ^ swz);
    }

    if (BMT == 64) {
        load_tile(0);
        load_tile(1);
        for (int kt = 0; kt < nK; kt += 2) {
            CP_WAIT(0);
            __syncthreads();
            if (kt + 2 < nK) {
                load_tile(kt + 2);
                load_tile(kt + 3);
            }
#pragma unroll
            for (int half = 0; half < 2; half++) {
                const uint32_t* Asb = smu + ((kt + half) % NSTG) * SSTRIDE;
                const uint32_t* Bsb = Asb + ASIZE;
#pragma unroll
                for (int ks = 0; ks < 2; ks++) {
                    MMA_BLOCK_TM(acc, Asb, Bsb, arow, brow, o1v[ks], o2v[ks]);
                }
            }
        }
    } else {
        load_tile(0);
        load_tile(1);
        for (int kt = 0; kt < nK; kt++) {
            if (kt + 1 < nK) { CP_WAIT(1); } else { CP_WAIT(0); }
            __syncthreads();
            if (kt + 2 < nK) load_tile(kt + 2);
            const uint32_t* Asb = smu + (kt % NSTG) * SSTRIDE;
            const uint32_t* Bsb = Asb + ASIZE;
#pragma unroll
            for (int ks = 0; ks < 2; ks++) {
                MMA_BLOCK_ILV(acc, Asb, Bsb, arow, brow, o1v[ks], o2v[ks], NI);
            }
        }
    }

    // Epilogue. c0:(g,2t) c1:(g,2t+1) c2:(g+8,2t) c3:(g+8,2t+1)
    int mrow = m0 + wm * 32 + g;
    int rsel = mrow & 3;
    int nc0 = n0 + wn * ((BMT == 128) ? 64 : 32) + 2 * kc;
    const uint32_t* Rp = (const uint32_t*)resid;
    const float* Rf = (const float*)resid;
#pragma unroll
    for (int ni = 0; ni < NI; ni++) {
        int n = nc0 + ni * 8;
        int boff = BIAS2D ? rsel * Ng : 0;
        float bv0 = bias[boff + n], bv1 = bias[boff + n + 1];
#pragma unroll
        for (int mi = 0; mi < 2; mi++) {
#pragma unroll
            for (int h2 = 0; h2 < 2; h2++) {
                int m = mrow + mi * 16 + h2 * 8;
                float x0 = acc[mi][ni][2 * h2]     + bv0;
                float x1 = acc[mi][ni][2 * h2 + 1] + bv1;
                if (RESID == 1) {
                    uint2 rv = *(const uint2*)(Rp + (size_t)m * Ng + n);
                    float2 rh = bf2_unpack(rv.x), rl = bf2_unpack(rv.y);
                    x0 += rh.x + rl.x;
                    x1 += rh.y + rl.y;
                } else if (RESID == 2) {
                    size_t rr = RBCAST ? ((size_t)(m >> 2) * Ng + n)
                                       : ((size_t)m * Ng + n);
                    x0 += Rf[rr];
                    x1 += Rf[rr + 1];
                }
                if (RELU) { x0 = fmaxf(x0, 0.f); x1 = fmaxf(x1, 0.f); }
                if (PERM) {
                    int bb = m >> 14;
                    size_t low = (size_t)(m & 16383);
                    C[(((size_t)(bb * 128 + n)) << 14) + low] = x0;
                    C[(((size_t)(bb * 128 + n + 1)) << 14) + low] = x1;
                } else if (PACKOUT) {
                    uint2 pw = pack_hilo(x0, x1);
                    *(uint2*)((uint32_t*)C + (size_t)m * Ng + n) = pw;
                } else {
                    *(float2*)(C + (size_t)m * Ng + n) = make_float2(x0, x1);
                }
            }
        }
    }
}

// ---------------- fused qf2 + Y kernel (BM=64, term-major mma) --------------
__global__ void __launch_bounds__(256, 2)
fused_qf2_y(const uint32_t* __restrict__ qf, const uint32_t* __restrict__ wes,
            const float* __restrict__ b_end, const uint32_t* __restrict__ featT,
            const uint32_t* __restrict__ w1cds, const float* __restrict__ b_mlp1,
            float* __restrict__ Y) {
    extern __shared__ uint32_t smu[];
    uint32_t* Hs = smu;                     // 4 tiles x 2048 u32 = 8192
    const uint32_t PIPE = 8192;             // 3 stages x (A 2048 + B 4096)
    const int SSTRIDE = 6144;
    int tid = threadIdx.x;
    int lane = tid & 31, wid = tid >> 5;
    int wm = wid & 1, wn = wid >> 1;
    int m0 = blockIdx.x << 6;
    uint32_t smbase = smem_u32(smu);

    int g = lane >> 2, kc = lane & 3;
    int swz = (g & 3) << 2;
    int arow = wm * 32 + g;
    int brow = wn * 32 + g;
    int o1v[2], o2v[2];
#pragma unroll
    for (int ks = 0; ks < 2; ks++) {
        o1v[ks] = 2 * ((ks * 8 + kc) ^ swz);
        o2v[ks] = 2 * ((ks * 8 + kc + 4) ^ swz);
    }

    int rowA[2], jA[2];
    uint32_t saA[2];
#pragma unroll
    for (int i = 0; i < 2; i++) {
        int c = tid + (i << 8);
        int row = c >> 3, j = c & 7;
        rowA[i] = row; jA[i] = j;
        int ch = j ^ ((row & 3) << 1);
        saA[i] = (row << 5) + (ch << 2);
    }
    int rowB[4], jB[4];
    uint32_t saB[4];
#pragma unroll
    for (int i = 0; i < 4; i++) {
        int c = tid + (i << 8);
        int row = c >> 3, j = c & 7;
        rowB[i] = row; jB[i] = j;
        int ch = j ^ ((row & 3) << 1);
        saB[i] = 2048 + (row << 5) + (ch << 2);
    }

    // ===== Phase 1: qf2 tile (K=128, 4 k-tiles, 3-stage) =====
    {
        auto load1 = [&](int kt) {
            uint32_t st = PIPE + (kt % 3) * SSTRIDE;
#pragma unroll
            for (int i = 0; i < 2; i++)
                CP_ASYNC(smbase + ((st + saA[i]) << 2),
                         qf + (size_t)(m0 + rowA[i]) * 128 + (kt << 5) + (jA[i] << 2));
#pragma unroll
            for (int i = 0; i < 4; i++)
                CP_ASYNC(smbase + ((st + saB[i]) << 2),
                         wes + (size_t)rowB[i] * 128 + (kt << 5) + (jB[i] << 2));
            CP_COMMIT();
        };
        load1(0);
        load1(1);
        float acc[2][4][4];
#pragma unroll
        for (int mi = 0; mi < 2; mi++)
#pragma unroll
            for (int ni = 0; ni < 4; ni++)
#pragma unroll
                for (int u = 0; u < 4; u++) acc[mi][ni][u] = 0.f;
        for (int kt = 0; kt < 4; kt++) {
            if (kt < 3) { CP_WAIT(1); } else { CP_WAIT(0); }
            __syncthreads();
            if (kt + 2 < 4) load1(kt + 2);
            const uint32_t* Asb = smu + PIPE + (kt % 3) * SSTRIDE;
            const uint32_t* Bsb = Asb + 2048;
#pragma unroll
            for (int ks = 0; ks < 2; ks++) {
                MMA_BLOCK_TM(acc, Asb, Bsb, arow, brow, o1v[ks], o2v[ks]);
            }
        }
        int nc0 = wn * 32 + 2 * kc;
#pragma unroll
        for (int ni = 0; ni < 4; ni++) {
            int n = nc0 + ni * 8;
            float bv0 = b_end[n], bv1 = b_end[n + 1];
#pragma unroll
            for (int mi = 0; mi < 2; mi++) {
#pragma unroll
                for (int h2 = 0; h2 < 2; h2++) {
                    int ml = arow + mi * 16 + h2 * 8;
                    uint2 rv = *(const uint2*)(featT + ((size_t)(m0 + ml) << 7) + n);
                    float2 rh = bf2_unpack(rv.x), rl = bf2_unpack(rv.y);
                    float x0 = acc[mi][ni][2 * h2]     + bv0 + rh.x + rl.x;
                    float x1 = acc[mi][ni][2 * h2 + 1] + bv1 + rh.y + rl.y;
                    x0 = fmaxf(x0, 0.f);
                    x1 = fmaxf(x1, 0.f);
                    uint2 pw = pack_hilo(x0, x1);
                    int p = n >> 1;
                    uint32_t off = (uint32_t)(p >> 4) * 2048 + (ml << 5)
                                 + 2 * ((p & 15) ^ ((ml & 3) << 2));
                    *(uint2*)(Hs + off) = pw;
                }
            }
        }
    }

    // ===== Phase 2: Y, two n-passes, K=256 (kt<4 from Hs, kt>=4 featT) =====
#pragma unroll 1
    for (int np = 0; np < 2; np++) {
        __syncthreads();
        const uint32_t* Bb = w1cds + ((size_t)np << 15);
        auto load2 = [&](int kt) {
            uint32_t st = PIPE + (kt % 3) * SSTRIDE;
            if (kt >= 4) {
#pragma unroll
                for (int i = 0; i < 2; i++)
                    CP_ASYNC(smbase + ((st + saA[i]) << 2),
                             featT + ((size_t)(m0 + rowA[i]) << 7) + ((kt - 4) << 5) + (jA[i] << 2));
            }
#pragma unroll
            for (int i = 0; i < 4; i++)
                CP_ASYNC(smbase + ((st + saB[i]) << 2),
                         Bb + (size_t)rowB[i] * 256 + (kt << 5) + (jB[i] << 2));
            CP_COMMIT();
        };
        load2(0);
        load2(1);
        float acc[2][4][4];
#pragma unroll
        for (int mi = 0; mi < 2; mi++)
#pragma unroll
            for (int ni = 0; ni < 4; ni++)
#pragma unroll
                for (int u = 0; u < 4; u++) acc[mi][ni][u] = 0.f;
        for (int kt = 0; kt < 8; kt++) {
            if (kt < 7) { CP_WAIT(1); } else { CP_WAIT(0); }
            __syncthreads();
            if (kt + 2 < 8) load2(kt + 2);
            const uint32_t* slot = smu + PIPE + (kt % 3) * SSTRIDE;
            const uint32_t* Asb = (kt < 4) ? (Hs + kt * 2048) : slot;
            const uint32_t* Bsb = slot + 2048;
#pragma unroll
            for (int ks = 0; ks < 2; ks++) {
                MMA_BLOCK_TM(acc, Asb, Bsb, arow, brow, o1v[ks], o2v[ks]);
            }
        }
        int nc0 = (np << 7) + wn * 32 + 2 * kc;
#pragma unroll
        for (int ni = 0; ni < 4; ni++) {
            int n = nc0 + ni * 8;
            float bv0 = b_mlp1[n], bv1 = b_mlp1[n + 1];
#pragma unroll
            for (int mi = 0; mi < 2; mi++) {
#pragma unroll
                for (int h2 = 0; h2 < 2; h2++) {
                    int m = m0 + arow + mi * 16 + h2 * 8;
                    float x0 = acc[mi][ni][2 * h2]     + bv0;
                    float x1 = acc[mi][ni][2 * h2 + 1] + bv1;
                    *(float2*)(Y + ((size_t)m << 8) + n) = make_float2(x0, x1);
                }
            }
        }
    }
}

// -------- kernel-point correlation: packed feat0 -> packed wf --------------
__global__ void kp_wf_kernel(const float* __restrict__ pos,
                             const int* __restrict__ idx,
                             const float* __restrict__ qp,
                             const uint32_t* __restrict__ feat0,
                             uint32_t* __restrict__ wf) {
    int s = blockIdx.x;
    int b = s >> 12, n = s & (BQ_N - 1);
    int c = threadIdx.x;
    __shared__ float wsh[R1][KN];
    __shared__ int nidx[KN];
    if (c < KN) {
        int m = idx[(size_t)s * KN + c];
        nidx[c] = m;
        float wr[R1];
#pragma unroll
        for (int r = 0; r < R1; r++) wr[r] = 0.f;
        if (m < BQ_N) {
            const float* p = pos + (size_t)b * 3 * BQ_N;
            float rx = p[m] - p[n];
            float ry = p[BQ_N + m] - p[BQ_N + n];
            float rz = p[2 * BQ_N + m] - p[2 * BQ_N + n];
#pragma unroll
            for (int r = 0; r < R1; r++) {
                float dx = rx - qp[r];
                float dy = ry - qp[R1 + r];
                float dz = rz - qp[2 * R1 + r];
                float d = sqrtf(dx * dx + dy * dy + dz * dz);
                wr[r] = fmaxf(0.f, 1.f - d / 0.1f);
            }
        }
#pragma unroll
        for (int r = 0; r < R1; r++) wsh[r][c] = wr[r];
    }
    __syncthreads();
    float acc[R1] = {0.f, 0.f, 0.f, 0.f, 0.f};
    bool odd = (c & 1);
    int ce = c & ~1;
#pragma unroll 4
    for (int k = 0; k < KN; k++) {
        int m = nidx[k];
        float f = 0.f;
        if (m < BQ_N) {
            uint2 w = *(const uint2*)(feat0 + (((size_t)(b * BQ_N + m)) << 7) + ce);
            float2 hh = bf2_unpack(w.x), ll = bf2_unpack(w.y);
            f = odd ? (hh.y + ll.y) : (hh.x + ll.x);
        }
#pragma unroll
        for (int r = 0; r < R1; r++) acc[r] += wsh[r][k] * f;
    }
#pragma unroll
    for (int r = 0; r < R1; r++) {
        float v = acc[r];
        float vp = __shfl_xor_sync(0xffffffffu, v, 1);
        if (!odd) {
            uint2 pw = pack_hilo(v, vp);
            *(uint2*)(wf + (size_t)s * 640 + r * 128 + c) = pw;
        }
    }
}

// ---- setup: transpose(+pack) | ballquery | prep, by blockIdx range --------
#define T_BLOCKS 2048
#define B_BLOCKS 2048         // 1 point per warp, direct LDG
#define PREP_TOTAL (8192 + 40960 + 8192 + 16384 + 32768 + 16384 + 1024 + 12)
#define P_BLOCKS ((PREP_TOTAL + 255) / 256)

__global__ void __launch_bounds__(256) setup_kernel(
    const float* __restrict__ feat, const float* __restrict__ pos,
    const float* __restrict__ w_begin, const float* __restrict__ kpw,
    const float* __restrict__ w_end, const float* __restrict__ w1,
    const float* __restrict__ w2, const float* __restrict__ qp,
    uint32_t* __restrict__ featT, int* __restrict__ idx,
    uint32_t* __restrict__ wbs, uint32_t* __restrict__ kpTs,
    uint32_t* __restrict__ wes, uint32_t* __restrict__ w1as,
    uint32_t* __restrict__ w1cds, uint32_t* __restrict__ m2s,
    float* __restrict__ bias2d, float* __restrict__ out12) {
    extern __shared__ float dynf[];
    int bid = blockIdx.x;
    int tid = threadIdx.x;
    if (bid < T_BLOCKS) {
        float (*tile)[33] = (float (*)[33])dynf;
        int b = bid >> 9;
        int n0 = (bid & 127) * 32, c0 = ((bid >> 7) & 3) * 32;
        int tx = tid & 31, ty = tid >> 5;
#pragma unroll
        for (int i = ty; i < 32; i += 8)
            tile[i][tx] = feat[((size_t)(b * CC + c0 + i)) * BQ_N + n0 + tx];
        __syncthreads();
#pragma unroll
        for (int i = ty; i < 32; i += 8) {
            float v = tile[tx][i];
            float vp = __shfl_xor_sync(0xffffffffu, v, 1);
            if (!(tx & 1)) {
                uint2 pw = pack_hilo(v, vp);
                *(uint2*)(featT + (((size_t)(b * BQ_N + n0 + i)) << 7) + c0 + tx) = pw;
            }
        }
        return;
    }
    if (bid < T_BLOCKS + B_BLOCKS) {
        int t = bid - T_BLOCKS;
        int b = t >> 9, bx = t & 511;
        const float* px = pos + (size_t)b * 3 * BQ_N;
        const float* py = px + BQ_N;
        const float* pz = px + 2 * BQ_N;
        int warp = tid >> 5, lane = tid & 31;
        int n = bx * 8 + warp;
        float xn = px[n], yn = py[n], zn = pz[n];
        float nn = xn * xn + yn * yn + zn * zn;
        int* out = idx + (size_t)(b * BQ_N + n) * KN;
        int count = 0;
        for (int m0 = 0; m0 < BQ_N && count < KN; m0 += 32) {
            int m = m0 + lane;
            float xm = px[m], ym = py[m], zm = pz[m];
            float nm = xm * xm + ym * ym + zm * zm;
            float dt = xn * xm + yn * ym + zn * zm;
            float sqd = (nn + nm) - 2.0f * dt;
            bool ok = (sqd <= CONV_R2);
            unsigned msk = __ballot_sync(0xffffffffu, ok);
            int p2 = count + __popc(msk & ((1u << lane) - 1u));
            if (ok && p2 < KN) out[p2] = m;
            count += __popc(msk);
            if (count > KN) count = KN;
        }
        for (int p2 = count + lane; p2 < KN; p2 += 32) out[p2] = BQ_N;
        return;
    }
    int t = (bid - T_BLOCKS - B_BLOCKS) * 256 + tid;
    if (t < 8192) {
        int o = t >> 6, p = t & 63;
        *(uint2*)(wbs + o * 128 + 2 * p) =
            pack_hilo(w_begin[o * 128 + 2 * p], w_begin[o * 128 + 2 * p + 1]);
        return;
    }
    t -= 8192;
    if (t < 40960) {
        int c = t / 320, p = t % 320;
        *(uint2*)(kpTs + (size_t)c * 640 + 2 * p) =
            pack_hilo(kpw[(size_t)(2 * p) * 128 + c], kpw[(size_t)(2 * p + 1) * 128 + c]);
        return;
    }
    t -= 40960;
    if (t < 8192) {
        int o = t >> 6, p = t & 63;
        *(uint2*)(wes + o * 128 + 2 * p) =
            pack_hilo(w_end[o * 128 + 2 * p], w_end[o * 128 + 2 * p + 1]);
        return;
    }
    t -= 8192;
    if (t < 16384) {
        int o = t >> 6, p = t & 63;
        *(uint2*)(w1as + o * 128 + 2 * p) =
            pack_hilo(w1[(size_t)o * 387 + 2 * p], w1[(size_t)o * 387 + 2 * p + 1]);
        return;
    }
    t -= 16384;
    if (t < 32768) {
        int o = t >> 7, p = t & 127;
        *(uint2*)(w1cds + (size_t)o * 256 + 2 * p) =
            pack_hilo(w1[(size_t)o * 387 + 131 + 2 * p], w1[(size_t)o * 387 + 132 + 2 * p]);
        return;
    }
    t -= 32768;
    if (t < 16384) {
        int o = t >> 7, p = t & 127;
        *(uint2*)(m2s + (size_t)o * 256 + 2 * p) =
            pack_hilo(w2[(size_t)o * 256 + 2 * p], w2[(size_t)o * 256 + 2 * p + 1]);
        return;
    }
    t -= 16384;
    if (t < 1024) {
        int r = t >> 8, n = t & 255;
        float s = 0.f;
#pragma unroll
        for (int a = 0; a < 3; a++)
            s += w1[(size_t)n * 387 + 128 + a] * qp[a * R1 + r + 1];
        bias2d[r * 256 + n] = s;
        return;
    }
    t -= 1024;
    if (t >= 0 && t < 12) {
        int a = t >> 2, r = (t & 3) + 1;
        out12[t] = qp[a * R1 + r];
    }
}

// ---------------- launch ----------------------------------------------------
extern "C" void kernel_launch(void* const* d_in, const int* in_sizes, int n_in,
                              void* d_out, int out_size) {
    (void)in_sizes; (void)n_in; (void)out_size;
    const float* pos       = (const float*)d_in[0];
    const float* feat      = (const float*)d_in[1];
    const float* qp        = (const float*)d_in[2];
    const float* w_begin   = (const float*)d_in[3];
    const float* b_begin   = (const float*)d_in[4];
    const float* kp_weight = (const float*)d_in[5];
    const float* kp_bias   = (const float*)d_in[6];
    const float* w_end     = (const float*)d_in[7];
    const float* b_end     = (const float*)d_in[8];
    const float* w_mlp1    = (const float*)d_in[9];
    const float* b_mlp1    = (const float*)d_in[10];
    const float* w_mlp2    = (const float*)d_in[11];
    const float* b_mlp2    = (const float*)d_in[12];
    float* out = (float*)d_out;

    uint32_t *featT, *feat0, *wf, *qf, *h;
    uint32_t *wbs, *kpTs, *wes, *w1as, *w1cds, *m2s;
    float *Y, *bias2d;
    int* idx;
    cudaGetSymbolAddress((void**)&featT, g_featT);
    cudaGetSymbolAddress((void**)&feat0, g_feat0);
    cudaGetSymbolAddress((void**)&idx,   g_idx);
    cudaGetSymbolAddress((void**)&wf,    g_wf);
    cudaGetSymbolAddress((void**)&qf,    g_qf);
    cudaGetSymbolAddress((void**)&Y,     g_Y);
    cudaGetSymbolAddress((void**)&h,     g_h);
    cudaGetSymbolAddress((void**)&wbs,   g_wbs);
    cudaGetSymbolAddress((void**)&kpTs,  g_kpTs);
    cudaGetSymbolAddress((void**)&wes,   g_wes);
    cudaGetSymbolAddress((void**)&w1as,  g_w1as);
    cudaGetSymbolAddress((void**)&w1cds, g_w1cds);
    cudaGetSymbolAddress((void**)&m2s,   g_m2s);
    cudaGetSymbolAddress((void**)&bias2d, g_bias2d);

    const int SMEM_SETUP = 32 * 33 * 4 + 256;
    const int SMEM_S = 4 * (64 * 32 + 4096) * 4;    // 98304 B
    const int SMEM_B = 3 * (128 * 32 + 4096) * 4;   // 98304 B
    const int SMEM_F = (8192 + 3 * 6144) * 4;       // 106496 B
    cudaFuncSetAttribute(setup_kernel,
                         cudaFuncAttributeMaxDynamicSharedMemorySize, SMEM_SETUP);
    cudaFuncSetAttribute(fused_qf2_y,
                         cudaFuncAttributeMaxDynamicSharedMemorySize, SMEM_F);
#define SETSM(SM, ...) cudaFuncSetAttribute(mma_gemm<__VA_ARGS__>, \
        cudaFuncAttributeMaxDynamicSharedMemorySize, SM)
    SETSM(SMEM_S, 64,  0, false, 0, false, false, false, true);
    SETSM(SMEM_S, 64,  0, true,  0, false, false, false, true);
    SETSM(SMEM_B, 128, 1, true,  2, true,  true,  false, true);
    SETSM(SMEM_B, 128, 0, true,  0, false, false, true,  false);
#undef SETSM

    // Stage 0: fused transpose + ball query + prep
    setup_kernel<<<T_BLOCKS + B_BLOCKS + P_BLOCKS, 256, SMEM_SETUP>>>(
        feat, pos, w_begin, kp_weight, w_end, w_mlp1, w_mlp2, qp,
        featT, idx, wbs, kpTs, wes, w1as, w1cds, m2s, bias2d, out);

    // feat0 = featT @ w_begin^T + b_begin          (packed out)
    mma_gemm<64, 0, false, 0, false, false, false, true><<<dim3(1, 256), 256, SMEM_S>>>(
        S_TOT, 128, 128, featT, wbs, b_begin, nullptr, (float*)feat0);

    // kernel-point correlation -> wf (S, 640)      (packed out)
    kp_wf_kernel<<<S_TOT, 128>>>(pos, idx, qp, feat0, wf);

    // qf = relu(wf @ kpT^T + kp_bias)              (packed out)
    mma_gemm<64, 0, true, 0, false, false, false, true><<<dim3(1, 256), 256, SMEM_S>>>(
        S_TOT, 128, 640, wf, kpTs, kp_bias, nullptr, (float*)qf);

    // fused: qf2 (smem only) -> Y = [qf2|featT] @ w1cd^T + b_mlp1
    fused_qf2_y<<<256, 256, SMEM_F>>>(qf, wes, b_end, featT, w1cds, b_mlp1, Y);

    // h = relu(wf_r @ w1a^T + bias2d[r] + Y[s])    (packed out)
    mma_gemm<128, 1, true, 2, true, true, false, true><<<dim3(2, 512), 256, SMEM_B>>>(
        S2_TOT, 256, 128, wf, w1as, bias2d, Y, (float*)h);

    // queries = relu(h @ w_mlp2^T + b_mlp2), scattered to (B, TD, N, R)
    mma_gemm<128, 0, true, 0, false, false, true, false><<<dim3(1, 512), 256, SMEM_B>>>(
        S2_TOT, 128, 256, h, m2s, b_mlp2, nullptr, out + 12);
}

// round 16
// speedup vs baseline: 1.0498x; 1.0227x over previous
#include <cuda_runtime.h>
#include <cuda_bf16.h>
#include <cstdint>

// Problem constants (fixed shapes)
#define BQ_N 4096
#define NB 4
#define CC 128
#define KN 32
#define R1 5
#define S_TOT (NB * BQ_N)        // 16384 samples
#define S2_TOT (S_TOT * 4)       // 65536 (sample, r) columns
#define CONV_R2 0.04f            // (0.2)^2

// ---------------- scratch (device globals; no allocation allowed) ----------
__device__ uint32_t g_featT[S_TOT * CC];
__device__ uint32_t g_feat0[S_TOT * CC];
__device__ int      g_idx[S_TOT * KN];
__device__ uint32_t g_wf[(size_t)S_TOT * R1 * CC];
__device__ uint32_t g_qf[S_TOT * CC];
__device__ float    g_Y[(size_t)S_TOT * 256];       // fp32 (resid only)
__device__ uint32_t g_h[(size_t)S2_TOT * 256];
// packed weights (N, K) u32
__device__ uint32_t g_wbs[128 * 128];
__device__ uint32_t g_kpTs[128 * 640];
__device__ uint32_t g_wes[128 * 128];
__device__ uint32_t g_w1as[256 * 128];
__device__ uint32_t g_w1cds[256 * 256];
__device__ uint32_t g_m2s[128 * 256];
__device__ float    g_bias2d[4 * 256];

__device__ __forceinline__ uint32_t smem_u32(const void* p) {
    uint32_t a;
    asm("{ .reg .u64 t; cvta.to.shared.u64 t, %1; cvt.u32.u64 %0, t; }"
        : "=r"(a) : "l"(p));
    return a;
}

__device__ __forceinline__ uint32_t bf2_pack(float v0, float v1) {
    __nv_bfloat162 h = __floats2bfloat162_rn(v0, v1);
    return *reinterpret_cast<uint32_t*>(&h);
}
__device__ __forceinline__ float2 bf2_unpack(uint32_t u) {
    __nv_bfloat162 h = *reinterpret_cast<__nv_bfloat162*>(&u);
    return make_float2(__bfloat162float(h.x), __bfloat162float(h.y));
}
__device__ __forceinline__ uint2 pack_hilo(float v0, float v1) {
    uint32_t hi = bf2_pack(v0, v1);
    float2 hf = bf2_unpack(hi);
    uint32_t lo = bf2_pack(v0 - hf.x, v1 - hf.y);
    return make_uint2(hi, lo);
}

#define CP_ASYNC(sa, g) \
    asm volatile("cp.async.cg.shared.global [%0], [%1], 16;" :: "r"(sa), "l"(g) : "memory")
#define CP_COMMIT() asm volatile("cp.async.commit_group;" ::: "memory")
#define CP_WAIT(n)  asm volatile("cp.async.wait_group %0;" :: "n"(n) : "memory")

#define MMA_BF16(d, a0, a1, a2, a3, b0, b1) \
    asm volatile( \
        "mma.sync.aligned.m16n8k16.row.col.f32.bf16.bf16.f32 " \
        "{%0,%1,%2,%3}, {%4,%5,%6,%7}, {%8,%9}, {%0,%1,%2,%3};" \
        : "+f"((d)[0]), "+f"((d)[1]), "+f"((d)[2]), "+f"((d)[3]) \
        : "r"(a0), "r"(a1), "r"(a2), "r"(a3), "r"(b0), "r"(b1))

// TERM-MAJOR order (NI=4): all lo*hi, all hi*lo, all hi*hi across the 8
// (ni x mi) accumulators -> dependent reuse distance 8 issues, hides HMMA
// latency. Per-accumulator term order unchanged -> numerics identical.
#define MMA_BLOCK_TM(ACC, Asb, Bsb, arow, brow, o1, o2)                       \
    {                                                                          \
        uint2 Af[2][4];                                                        \
        _Pragma("unroll")                                                      \
        for (int mi = 0; mi < 2; mi++) {                                       \
            const uint32_t* p = (Asb) + (((arow) + mi * 16) << 5);             \
            Af[mi][0] = *(const uint2*)(p + (o1));                             \
            Af[mi][1] = *(const uint2*)(p + 256 + (o1));                       \
            Af[mi][2] = *(const uint2*)(p + (o2));                             \
            Af[mi][3] = *(const uint2*)(p + 256 + (o2));                       \
        }                                                                      \
        uint2 Bf0[4], Bf1[4];                                                  \
        _Pragma("unroll")                                                      \
        for (int q = 0; q < 4; q++) {                                          \
            const uint32_t* bp = (Bsb) + (((brow) + q * 8) << 5);              \
            Bf0[q] = *(const uint2*)(bp + (o1));                               \
            Bf1[q] = *(const uint2*)(bp + (o2));                               \
        }                                                                      \
        _Pragma("unroll")                                                      \
        for (int q = 0; q < 4; q++)                                            \
            _Pragma("unroll")                                                  \
            for (int mi = 0; mi < 2; mi++)                                     \
                MMA_BF16(ACC[mi][q], Af[mi][0].y, Af[mi][1].y,                 \
                         Af[mi][2].y, Af[mi][3].y, Bf0[q].x, Bf1[q].x);        \
        _Pragma("unroll")                                                      \
        for (int q = 0; q < 4; q++)                                            \
            _Pragma("unroll")                                                  \
            for (int mi = 0; mi < 2; mi++)                                     \
                MMA_BF16(ACC[mi][q], Af[mi][0].x, Af[mi][1].x,                 \
                         Af[mi][2].x, Af[mi][3].x, Bf0[q].y, Bf1[q].y);        \
        _Pragma("unroll")                                                      \
        for (int q = 0; q < 4; q++)                                            \
            _Pragma("unroll")                                                  \
            for (int mi = 0; mi < 2; mi++)                                     \
                MMA_BF16(ACC[mi][q], Af[mi][0].x, Af[mi][1].x,                 \
                         Af[mi][2].x, Af[mi][3].x, Bf0[q].x, Bf1[q].x);        \
    }

// ---------------- bf16x3 mma.sync GEMM, packed hi/lo, hoisted pointers ------
// BMT=64 only now: PAIR mainloop (2 k-tiles/sync), TERM-MAJOR mma, 4 slots.
// C[M, 128-tile of Ng] = epi(A @ B^T + bias).
// AMODE 0: row-major (M,K). 1: m -> wf[s=m>>2] slice (m&3)+1 (K=128).
// RESID 0: none; 1: packed bf16 hi/lo; 2: fp32 (RBCAST: row m>>2).
template <int AMODE, bool RELU, int RESID, bool RBCAST, bool BIAS2D,
          bool PERM, bool PACKOUT>
__global__ void __launch_bounds__(256, 2)
mma_gemm(int M, int Ng, int K,
         const uint32_t* __restrict__ A,
         const uint32_t* __restrict__ Bs,
         const float* __restrict__ bias, const void* __restrict__ resid,
         float* __restrict__ C) {
    extern __shared__ uint32_t smu[];
    constexpr int ASIZE = 64 * 32;
    constexpr int SSTRIDE = ASIZE + 4096;
    constexpr int NSTG = 4;
    int tid = threadIdx.x;
    int lane = tid & 31, wid = tid >> 5;
    int wm = wid & 1, wn = wid >> 1;
    int m0 = blockIdx.y << 6, n0 = blockIdx.x << 7;
    int nK = K >> 5;
    uint32_t smbase = smem_u32(smu);

    const uint32_t* gA[2];
    uint32_t saA[2];
#pragma unroll
    for (int i = 0; i < 2; i++) {
        int c = tid + (i << 8);
        int row = c >> 3, j = c & 7;
        if (AMODE == 0) {
            gA[i] = A + (size_t)(m0 + row) * K + (j << 2);
        } else {
            int m = m0 + row;
            gA[i] = A + (size_t)(m >> 2) * 640 + (((m & 3) + 1) << 7) + (j << 2);
        }
        int ch = j ^ ((row & 3) << 1);
        saA[i] = (row << 5) + (ch << 2);
    }
    const uint32_t* gB[4];
    uint32_t saB[4];
#pragma unroll
    for (int i = 0; i < 4; i++) {
        int c = tid + (i << 8);
        int row = c >> 3, j = c & 7;
        gB[i] = Bs + (size_t)(n0 + row) * K + (j << 2);
        int ch = j ^ ((row & 3) << 1);
        saB[i] = ASIZE + (row << 5) + (ch << 2);
    }

    float acc[2][4][4];
#pragma unroll
    for (int mi = 0; mi < 2; mi++)
#pragma unroll
        for (int ni = 0; ni < 4; ni++)
#pragma unroll
            for (int u = 0; u < 4; u++) acc[mi][ni][u] = 0.f;

    auto load_tile = [&](int kt) {
        uint32_t st = (kt % NSTG) * SSTRIDE;
#pragma unroll
        for (int i = 0; i < 2; i++) {
            CP_ASYNC(smbase + ((st + saA[i]) << 2), gA[i]);
            gA[i] += 32;
        }
#pragma unroll
        for (int i = 0; i < 4; i++) {
            CP_ASYNC(smbase + ((st + saB[i]) << 2), gB[i]);
            gB[i] += 32;
        }
        CP_COMMIT();
    };

    int g = lane >> 2, kc = lane & 3;
    int swz = (g & 3) << 2;
    int arow = wm * 32 + g;
    int brow = wn * 32 + g;
    int o1v[2], o2v[2];
#pragma unroll
    for (int ks = 0; ks < 2; ks++) {
        o1v[ks] = 2 * ((ks * 8 + kc) ^ swz);
        o2v[ks] = 2 * ((ks * 8 + kc + 4) ^ swz);
    }

    // pair mainloop: one sync per 2 k-tiles (nK always even here)
    load_tile(0);
    load_tile(1);
    for (int kt = 0; kt < nK; kt += 2) {
        CP_WAIT(0);
        __syncthreads();
        if (kt + 2 < nK) {
            load_tile(kt + 2);
            load_tile(kt + 3);
        }
#pragma unroll
        for (int half = 0; half < 2; half++) {
            const uint32_t* Asb = smu + ((kt + half) % NSTG) * SSTRIDE;
            const uint32_t* Bsb = Asb + ASIZE;
#pragma unroll
            for (int ks = 0; ks < 2; ks++) {
                MMA_BLOCK_TM(acc, Asb, Bsb, arow, brow, o1v[ks], o2v[ks]);
            }
        }
    }

    // Epilogue. c0:(g,2t) c1:(g,2t+1) c2:(g+8,2t) c3:(g+8,2t+1)
    int mrow = m0 + wm * 32 + g;
    int rsel = mrow & 3;
    int nc0 = n0 + wn * 32 + 2 * kc;
    const uint32_t* Rp = (const uint32_t*)resid;
    const float* Rf = (const float*)resid;
#pragma unroll
    for (int ni = 0; ni < 4; ni++) {
        int n = nc0 + ni * 8;
        int boff = BIAS2D ? rsel * Ng : 0;
        float bv0 = bias[boff + n], bv1 = bias[boff + n + 1];
#pragma unroll
        for (int mi = 0; mi < 2; mi++) {
#pragma unroll
            for (int h2 = 0; h2 < 2; h2++) {
                int m = mrow + mi * 16 + h2 * 8;
                float x0 = acc[mi][ni][2 * h2]     + bv0;
                float x1 = acc[mi][ni][2 * h2 + 1] + bv1;
                if (RESID == 1) {
                    uint2 rv = *(const uint2*)(Rp + (size_t)m * Ng + n);
                    float2 rh = bf2_unpack(rv.x), rl = bf2_unpack(rv.y);
                    x0 += rh.x + rl.x;
                    x1 += rh.y + rl.y;
                } else if (RESID == 2) {
                    size_t rr = RBCAST ? ((size_t)(m >> 2) * Ng + n)
                                       : ((size_t)m * Ng + n);
                    x0 += Rf[rr];
                    x1 += Rf[rr + 1];
                }
                if (RELU) { x0 = fmaxf(x0, 0.f); x1 = fmaxf(x1, 0.f); }
                if (PERM) {
                    int bb = m >> 14;
                    size_t low = (size_t)(m & 16383);
                    C[(((size_t)(bb * 128 + n)) << 14) + low] = x0;
                    C[(((size_t)(bb * 128 + n + 1)) << 14) + low] = x1;
                } else if (PACKOUT) {
                    uint2 pw = pack_hilo(x0, x1);
                    *(uint2*)((uint32_t*)C + (size_t)m * Ng + n) = pw;
                } else {
                    *(float2*)(C + (size_t)m * Ng + n) = make_float2(x0, x1);
                }
            }
        }
    }
}

// ---------------- fused qf2 + Y kernel (BM=64, term-major mma) --------------
__global__ void __launch_bounds__(256, 2)
fused_qf2_y(const uint32_t* __restrict__ qf, const uint32_t* __restrict__ wes,
            const float* __restrict__ b_end, const uint32_t* __restrict__ featT,
            const uint32_t* __restrict__ w1cds, const float* __restrict__ b_mlp1,
            float* __restrict__ Y) {
    extern __shared__ uint32_t smu[];
    uint32_t* Hs = smu;                     // 4 tiles x 2048 u32 = 8192
    const uint32_t PIPE = 8192;             // 3 stages x (A 2048 + B 4096)
    const int SSTRIDE = 6144;
    int tid = threadIdx.x;
    int lane = tid & 31, wid = tid >> 5;
    int wm = wid & 1, wn = wid >> 1;
    int m0 = blockIdx.x << 6;
    uint32_t smbase = smem_u32(smu);

    int g = lane >> 2, kc = lane & 3;
    int swz = (g & 3) << 2;
    int arow = wm * 32 + g;
    int brow = wn * 32 + g;
    int o1v[2], o2v[2];
#pragma unroll
    for (int ks = 0; ks < 2; ks++) {
        o1v[ks] = 2 * ((ks * 8 + kc) ^ swz);
        o2v[ks] = 2 * ((ks * 8 + kc + 4) ^ swz);
    }

    int rowA[2], jA[2];
    uint32_t saA[2];
#pragma unroll
    for (int i = 0; i < 2; i++) {
        int c = tid + (i << 8);
        int row = c >> 3, j = c & 7;
        rowA[i] = row; jA[i] = j;
        int ch = j ^ ((row & 3) << 1);
        saA[i] = (row << 5) + (ch << 2);
    }
    int rowB[4], jB[4];
    uint32_t saB[4];
#pragma unroll
    for (int i = 0; i < 4; i++) {
        int c = tid + (i << 8);
        int row = c >> 3, j = c & 7;
        rowB[i] = row; jB[i] = j;
        int ch = j ^ ((row & 3) << 1);
        saB[i] = 2048 + (row << 5) + (ch << 2);
    }

    // ===== Phase 1: qf2 tile (K=128, 4 k-tiles, 3-stage) =====
    {
        auto load1 = [&](int kt) {
            uint32_t st = PIPE + (kt % 3) * SSTRIDE;
#pragma unroll
            for (int i = 0; i < 2; i++)
                CP_ASYNC(smbase + ((st + saA[i]) << 2),
                         qf + (size_t)(m0 + rowA[i]) * 128 + (kt << 5) + (jA[i] << 2));
#pragma unroll
            for (int i = 0; i < 4; i++)
                CP_ASYNC(smbase + ((st + saB[i]) << 2),
                         wes + (size_t)rowB[i] * 128 + (kt << 5) + (jB[i] << 2));
            CP_COMMIT();
        };
        load1(0);
        load1(1);
        float acc[2][4][4];
#pragma unroll
        for (int mi = 0; mi < 2; mi++)
#pragma unroll
            for (int ni = 0; ni < 4; ni++)
#pragma unroll
                for (int u = 0; u < 4; u++) acc[mi][ni][u] = 0.f;
        for (int kt = 0; kt < 4; kt++) {
            if (kt < 3) { CP_WAIT(1); } else { CP_WAIT(0); }
            __syncthreads();
            if (kt + 2 < 4) load1(kt + 2);
            const uint32_t* Asb = smu + PIPE + (kt % 3) * SSTRIDE;
            const uint32_t* Bsb = Asb + 2048;
#pragma unroll
            for (int ks = 0; ks < 2; ks++) {
                MMA_BLOCK_TM(acc, Asb, Bsb, arow, brow, o1v[ks], o2v[ks]);
            }
        }
        int nc0 = wn * 32 + 2 * kc;
#pragma unroll
        for (int ni = 0; ni < 4; ni++) {
            int n = nc0 + ni * 8;
            float bv0 = b_end[n], bv1 = b_end[n + 1];
#pragma unroll
            for (int mi = 0; mi < 2; mi++) {
#pragma unroll
                for (int h2 = 0; h2 < 2; h2++) {
                    int ml = arow + mi * 16 + h2 * 8;
                    uint2 rv = *(const uint2*)(featT + ((size_t)(m0 + ml) << 7) + n);
                    float2 rh = bf2_unpack(rv.x), rl = bf2_unpack(rv.y);
                    float x0 = acc[mi][ni][2 * h2]     + bv0 + rh.x + rl.x;
                    float x1 = acc[mi][ni][2 * h2 + 1] + bv1 + rh.y + rl.y;
                    x0 = fmaxf(x0, 0.f);
                    x1 = fmaxf(x1, 0.f);
                    uint2 pw = pack_hilo(x0, x1);
                    int p = n >> 1;
                    uint32_t off = (uint32_t)(p >> 4) * 2048 + (ml << 5)
                                 + 2 * ((p & 15) ^ ((ml & 3) << 2));
                    *(uint2*)(Hs + off) = pw;
                }
            }
        }
    }

    // ===== Phase 2: Y, two n-passes, K=256 (kt<4 from Hs, kt>=4 featT) =====
#pragma unroll 1
    for (int np = 0; np < 2; np++) {
        __syncthreads();
        const uint32_t* Bb = w1cds + ((size_t)np << 15);
        auto load2 = [&](int kt) {
            uint32_t st = PIPE + (kt % 3) * SSTRIDE;
            if (kt >= 4) {
#pragma unroll
                for (int i = 0; i < 2; i++)
                    CP_ASYNC(smbase + ((st + saA[i]) << 2),
                             featT + ((size_t)(m0 + rowA[i]) << 7) + ((kt - 4) << 5) + (jA[i] << 2));
            }
#pragma unroll
            for (int i = 0; i < 4; i++)
                CP_ASYNC(smbase + ((st + saB[i]) << 2),
                         Bb + (size_t)rowB[i] * 256 + (kt << 5) + (jB[i] << 2));
            CP_COMMIT();
        };
        load2(0);
        load2(1);
        float acc[2][4][4];
#pragma unroll
        for (int mi = 0; mi < 2; mi++)
#pragma unroll
            for (int ni = 0; ni < 4; ni++)
#pragma unroll
                for (int u = 0; u < 4; u++) acc[mi][ni][u] = 0.f;
        for (int kt = 0; kt < 8; kt++) {
            if (kt < 7) { CP_WAIT(1); } else { CP_WAIT(0); }
            __syncthreads();
            if (kt + 2 < 8) load2(kt + 2);
            const uint32_t* slot = smu + PIPE + (kt % 3) * SSTRIDE;
            const uint32_t* Asb = (kt < 4) ? (Hs + kt * 2048) : slot;
            const uint32_t* Bsb = slot + 2048;
#pragma unroll
            for (int ks = 0; ks < 2; ks++) {
                MMA_BLOCK_TM(acc, Asb, Bsb, arow, brow, o1v[ks], o2v[ks]);
            }
        }
        int nc0 = (np << 7) + wn * 32 + 2 * kc;
#pragma unroll
        for (int ni = 0; ni < 4; ni++) {
            int n = nc0 + ni * 8;
            float bv0 = b_mlp1[n], bv1 = b_mlp1[n + 1];
#pragma unroll
            for (int mi = 0; mi < 2; mi++) {
#pragma unroll
                for (int h2 = 0; h2 < 2; h2++) {
                    int m = m0 + arow + mi * 16 + h2 * 8;
                    float x0 = acc[mi][ni][2 * h2]     + bv0;
                    float x1 = acc[mi][ni][2 * h2 + 1] + bv1;
                    *(float2*)(Y + ((size_t)m << 8) + n) = make_float2(x0, x1);
                }
            }
        }
    }
}

// -------- kernel-point correlation: packed feat0 -> packed wf --------------
__global__ void kp_wf_kernel(const float* __restrict__ pos,
                             const int* __restrict__ idx,
                             const float* __restrict__ qp,
                             const uint32_t* __restrict__ feat0,
                             uint32_t* __restrict__ wf) {
    int s = blockIdx.x;
    int b = s >> 12, n = s & (BQ_N - 1);
    int c = threadIdx.x;
    __shared__ float wsh[R1][KN];
    __shared__ int nidx[KN];
    if (c < KN) {
        int m = idx[(size_t)s * KN + c];
        nidx[c] = m;
        float wr[R1];
#pragma unroll
        for (int r = 0; r < R1; r++) wr[r] = 0.f;
        if (m < BQ_N) {
            const float* p = pos + (size_t)b * 3 * BQ_N;
            float rx = p[m] - p[n];
            float ry = p[BQ_N + m] - p[BQ_N + n];
            float rz = p[2 * BQ_N + m] - p[2 * BQ_N + n];
#pragma unroll
            for (int r = 0; r < R1; r++) {
                float dx = rx - qp[r];
                float dy = ry - qp[R1 + r];
                float dz = rz - qp[2 * R1 + r];
                float d = sqrtf(dx * dx + dy * dy + dz * dz);
                wr[r] = fmaxf(0.f, 1.f - d / 0.1f);
            }
        }
#pragma unroll
        for (int r = 0; r < R1; r++) wsh[r][c] = wr[r];
    }
    __syncthreads();
    float acc[R1] = {0.f, 0.f, 0.f, 0.f, 0.f};
    bool odd = (c & 1);
    int ce = c & ~1;
#pragma unroll 4
    for (int k = 0; k < KN; k++) {
        int m = nidx[k];
        float f = 0.f;
        if (m < BQ_N) {
            uint2 w = *(const uint2*)(feat0 + (((size_t)(b * BQ_N + m)) << 7) + ce);
            float2 hh = bf2_unpack(w.x), ll = bf2_unpack(w.y);
            f = odd ? (hh.y + ll.y) : (hh.x + ll.x);
        }
#pragma unroll
        for (int r = 0; r < R1; r++) acc[r] += wsh[r][k] * f;
    }
#pragma unroll
    for (int r = 0; r < R1; r++) {
        float v = acc[r];
        float vp = __shfl_xor_sync(0xffffffffu, v, 1);
        if (!odd) {
            uint2 pw = pack_hilo(v, vp);
            *(uint2*)(wf + (size_t)s * 640 + r * 128 + c) = pw;
        }
    }
}

// ---- setup: transpose(+pack) | ballquery | prep, by blockIdx range --------
#define T_BLOCKS 2048
#define B_BLOCKS 2048         // 1 point per warp, direct LDG
#define PREP_TOTAL (8192 + 40960 + 8192 + 16384 + 32768 + 16384 + 1024 + 12)
#define P_BLOCKS ((PREP_TOTAL + 255) / 256)

__global__ void __launch_bounds__(256) setup_kernel(
    const float* __restrict__ feat, const float* __restrict__ pos,
    const float* __restrict__ w_begin, const float* __restrict__ kpw,
    const float* __restrict__ w_end, const float* __restrict__ w1,
    const float* __restrict__ w2, const float* __restrict__ qp,
    uint32_t* __restrict__ featT, int* __restrict__ idx,
    uint32_t* __restrict__ wbs, uint32_t* __restrict__ kpTs,
    uint32_t* __restrict__ wes, uint32_t* __restrict__ w1as,
    uint32_t* __restrict__ w1cds, uint32_t* __restrict__ m2s,
    float* __restrict__ bias2d, float* __restrict__ out12) {
    extern __shared__ float dynf[];
    int bid = blockIdx.x;
    int tid = threadIdx.x;
    if (bid < T_BLOCKS) {
        float (*tile)[33] = (float (*)[33])dynf;
        int b = bid >> 9;
        int n0 = (bid & 127) * 32, c0 = ((bid >> 7) & 3) * 32;
        int tx = tid & 31, ty = tid >> 5;
#pragma unroll
        for (int i = ty; i < 32; i += 8)
            tile[i][tx] = feat[((size_t)(b * CC + c0 + i)) * BQ_N + n0 + tx];
        __syncthreads();
#pragma unroll
        for (int i = ty; i < 32; i += 8) {
            float v = tile[tx][i];
            float vp = __shfl_xor_sync(0xffffffffu, v, 1);
            if (!(tx & 1)) {
                uint2 pw = pack_hilo(v, vp);
                *(uint2*)(featT + (((size_t)(b * BQ_N + n0 + i)) << 7) + c0 + tx) = pw;
            }
        }
        return;
    }
    if (bid < T_BLOCKS + B_BLOCKS) {
        int t = bid - T_BLOCKS;
        int b = t >> 9, bx = t & 511;
        const float* px = pos + (size_t)b * 3 * BQ_N;
        const float* py = px + BQ_N;
        const float* pz = px + 2 * BQ_N;
        int warp = tid >> 5, lane = tid & 31;
        int n = bx * 8 + warp;
        float xn = px[n], yn = py[n], zn = pz[n];
        float nn = xn * xn + yn * yn + zn * zn;
        int* out = idx + (size_t)(b * BQ_N + n) * KN;
        int count = 0;
        for (int m0 = 0; m0 < BQ_N && count < KN; m0 += 32) {
            int m = m0 + lane;
            float xm = px[m], ym = py[m], zm = pz[m];
            float nm = xm * xm + ym * ym + zm * zm;
            float dt = xn * xm + yn * ym + zn * zm;
            float sqd = (nn + nm) - 2.0f * dt;
            bool ok = (sqd <= CONV_R2);
            unsigned msk = __ballot_sync(0xffffffffu, ok);
            int p2 = count + __popc(msk & ((1u << lane) - 1u));
            if (ok && p2 < KN) out[p2] = m;
            count += __popc(msk);
            if (count > KN) count = KN;
        }
        for (int p2 = count + lane; p2 < KN; p2 += 32) out[p2] = BQ_N;
        return;
    }
    int t = (bid - T_BLOCKS - B_BLOCKS) * 256 + tid;
    if (t < 8192) {
        int o = t >> 6, p = t & 63;
        *(uint2*)(wbs + o * 128 + 2 * p) =
            pack_hilo(w_begin[o * 128 + 2 * p], w_begin[o * 128 + 2 * p + 1]);
        return;
    }
    t -= 8192;
    if (t < 40960) {
        int c = t / 320, p = t % 320;
        *(uint2*)(kpTs + (size_t)c * 640 + 2 * p) =
            pack_hilo(kpw[(size_t)(2 * p) * 128 + c], kpw[(size_t)(2 * p + 1) * 128 + c]);
        return;
    }
    t -= 40960;
    if (t < 8192) {
        int o = t >> 6, p = t & 63;
        *(uint2*)(wes + o * 128 + 2 * p) =
            pack_hilo(w_end[o * 128 + 2 * p], w_end[o * 128 + 2 * p + 1]);
        return;
    }
    t -= 8192;
    if (t < 16384) {
        int o = t >> 6, p = t & 63;
        *(uint2*)(w1as + o * 128 + 2 * p) =
            pack_hilo(w1[(size_t)o * 387 + 2 * p], w1[(size_t)o * 387 + 2 * p + 1]);
        return;
    }
    t -= 16384;
    if (t < 32768) {
        int o = t >> 7, p = t & 127;
        *(uint2*)(w1cds + (size_t)o * 256 + 2 * p) =
            pack_hilo(w1[(size_t)o * 387 + 131 + 2 * p], w1[(size_t)o * 387 + 132 + 2 * p]);
        return;
    }
    t -= 32768;
    if (t < 16384) {
        int o = t >> 7, p = t & 127;
        *(uint2*)(m2s + (size_t)o * 256 + 2 * p) =
            pack_hilo(w2[(size_t)o * 256 + 2 * p], w2[(size_t)o * 256 + 2 * p + 1]);
        return;
    }
    t -= 16384;
    if (t < 1024) {
        int r = t >> 8, n = t & 255;
        float s = 0.f;
#pragma unroll
        for (int a = 0; a < 3; a++)
            s += w1[(size_t)n * 387 + 128 + a] * qp[a * R1 + r + 1];
        bias2d[r * 256 + n] = s;
        return;
    }
    t -= 1024;
    if (t >= 0 && t < 12) {
        int a = t >> 2, r = (t & 3) + 1;
        out12[t] = qp[a * R1 + r];
    }
}

// ---------------- launch ----------------------------------------------------
extern "C" void kernel_launch(void* const* d_in, const int* in_sizes, int n_in,
                              void* d_out, int out_size) {
    (void)in_sizes; (void)n_in; (void)out_size;
    const float* pos       = (const float*)d_in[0];
    const float* feat      = (const float*)d_in[1];
    const float* qp        = (const float*)d_in[2];
    const float* w_begin   = (const float*)d_in[3];
    const float* b_begin   = (const float*)d_in[4];
    const float* kp_weight = (const float*)d_in[5];
    const float* kp_bias   = (const float*)d_in[6];
    const float* w_end     = (const float*)d_in[7];
    const float* b_end     = (const float*)d_in[8];
    const float* w_mlp1    = (const float*)d_in[9];
    const float* b_mlp1    = (const float*)d_in[10];
    const float* w_mlp2    = (const float*)d_in[11];
    const float* b_mlp2    = (const float*)d_in[12];
    float* out = (float*)d_out;

    uint32_t *featT, *feat0, *wf, *qf, *h;
    uint32_t *wbs, *kpTs, *wes, *w1as, *w1cds, *m2s;
    float *Y, *bias2d;
    int* idx;
    cudaGetSymbolAddress((void**)&featT, g_featT);
    cudaGetSymbolAddress((void**)&feat0, g_feat0);
    cudaGetSymbolAddress((void**)&idx,   g_idx);
    cudaGetSymbolAddress((void**)&wf,    g_wf);
    cudaGetSymbolAddress((void**)&qf,    g_qf);
    cudaGetSymbolAddress((void**)&Y,     g_Y);
    cudaGetSymbolAddress((void**)&h,     g_h);
    cudaGetSymbolAddress((void**)&wbs,   g_wbs);
    cudaGetSymbolAddress((void**)&kpTs,  g_kpTs);
    cudaGetSymbolAddress((void**)&wes,   g_wes);
    cudaGetSymbolAddress((void**)&w1as,  g_w1as);
    cudaGetSymbolAddress((void**)&w1cds, g_w1cds);
    cudaGetSymbolAddress((void**)&m2s,   g_m2s);
    cudaGetSymbolAddress((void**)&bias2d, g_bias2d);

    const int SMEM_SETUP = 32 * 33 * 4 + 256;
    const int SMEM_S = 4 * (64 * 32 + 4096) * 4;    // 98304 B (BM=64, 4 slots)
    const int SMEM_F = (8192 + 3 * 6144) * 4;       // 106496 B (fused qf2+Y)
    cudaFuncSetAttribute(setup_kernel,
                         cudaFuncAttributeMaxDynamicSharedMemorySize, SMEM_SETUP);
    cudaFuncSetAttribute(fused_qf2_y,
                         cudaFuncAttributeMaxDynamicSharedMemorySize, SMEM_F);
#define SETSM(...) cudaFuncSetAttribute(mma_gemm<__VA_ARGS__>, \
        cudaFuncAttributeMaxDynamicSharedMemorySize, SMEM_S)
    SETSM(0, false, 0, false, false, false, true);
    SETSM(0, true,  0, false, false, false, true);
    SETSM(1, true,  2, true,  true,  false, true);
    SETSM(0, true,  0, false, false, true,  false);
#undef SETSM

    // Stage 0: fused transpose + ball query + prep
    setup_kernel<<<T_BLOCKS + B_BLOCKS + P_BLOCKS, 256, SMEM_SETUP>>>(
        feat, pos, w_begin, kp_weight, w_end, w_mlp1, w_mlp2, qp,
        featT, idx, wbs, kpTs, wes, w1as, w1cds, m2s, bias2d, out);

    // feat0 = featT @ w_begin^T + b_begin          (packed out)
    mma_gemm<0, false, 0, false, false, false, true><<<dim3(1, 256), 256, SMEM_S>>>(
        S_TOT, 128, 128, featT, wbs, b_begin, nullptr, (float*)feat0);

    // kernel-point correlation -> wf (S, 640)      (packed out)
    kp_wf_kernel<<<S_TOT, 128>>>(pos, idx, qp, feat0, wf);

    // qf = relu(wf @ kpT^T + kp_bias)              (packed out)
    mma_gemm<0, true, 0, false, false, false, true><<<dim3(1, 256), 256, SMEM_S>>>(
        S_TOT, 128, 640, wf, kpTs, kp_bias, nullptr, (float*)qf);

    // fused: qf2 (smem only) -> Y = [qf2|featT] @ w1cd^T + b_mlp1
    fused_qf2_y<<<256, 256, SMEM_F>>>(qf, wes, b_end, featT, w1cds, b_mlp1, Y);

    // h = relu(wf_r @ w1a^T + bias2d[r] + Y[s])    (packed out, BM=64)
    mma_gemm<1, true, 2, true, true, false, true><<<dim3(2, 1024), 256, SMEM_S>>>(
        S2_TOT, 256, 128, wf, w1as, bias2d, Y, (float*)h);

    // queries = relu(h @ w_mlp2^T + b_mlp2), PERM scatter (BM=64)
    mma_gemm<0, true, 0, false, false, true, false><<<dim3(1, 1024), 256, SMEM_S>>>(
        S2_TOT, 128, 256, h, m2s, b_mlp2, nullptr, out + 12);
}

// round 17
// speedup vs baseline: 1.0693x; 1.0185x over previous
#include <cuda_runtime.h>
#include <cuda_bf16.h>
#include <cstdint>

// Problem constants (fixed shapes)
#define BQ_N 4096
#define NB 4
#define CC 128
#define KN 32
#define R1 5
#define S_TOT (NB * BQ_N)        // 16384 samples
#define S2_TOT (S_TOT * 4)       // 65536 (sample, r) columns
#define CONV_R2 0.04f            // (0.2)^2

// ---------------- scratch (device globals; no allocation allowed) ----------
__device__ uint32_t g_featT[S_TOT * CC];
__device__ uint32_t g_feat0[S_TOT * CC];
__device__ int      g_idx[S_TOT * KN];
__device__ uint32_t g_wf[(size_t)S_TOT * R1 * CC];
__device__ uint32_t g_qf[S_TOT * CC];
__device__ float    g_Y[(size_t)S_TOT * 256];       // fp32 (resid only)
__device__ uint32_t g_h[(size_t)S2_TOT * 256];
// packed weights (N, K) u32
__device__ uint32_t g_wbs[128 * 128];
__device__ uint32_t g_kpTs[128 * 640];
__device__ uint32_t g_wes[128 * 128];
__device__ uint32_t g_w1as[256 * 128];
__device__ uint32_t g_w1cds[256 * 256];
__device__ uint32_t g_m2s[128 * 256];
__device__ float    g_bias2d[4 * 256];

__device__ __forceinline__ uint32_t smem_u32(const void* p) {
    uint32_t a;
    asm("{ .reg .u64 t; cvta.to.shared.u64 t, %1; cvt.u32.u64 %0, t; }"
        : "=r"(a) : "l"(p));
    return a;
}

__device__ __forceinline__ uint32_t bf2_pack(float v0, float v1) {
    __nv_bfloat162 h = __floats2bfloat162_rn(v0, v1);
    return *reinterpret_cast<uint32_t*>(&h);
}
__device__ __forceinline__ float2 bf2_unpack(uint32_t u) {
    __nv_bfloat162 h = *reinterpret_cast<__nv_bfloat162*>(&u);
    return make_float2(__bfloat162float(h.x), __bfloat162float(h.y));
}
__device__ __forceinline__ uint2 pack_hilo(float v0, float v1) {
    uint32_t hi = bf2_pack(v0, v1);
    float2 hf = bf2_unpack(hi);
    uint32_t lo = bf2_pack(v0 - hf.x, v1 - hf.y);
    return make_uint2(hi, lo);
}

#define CP_ASYNC(sa, g) \
    asm volatile("cp.async.cg.shared.global [%0], [%1], 16;" :: "r"(sa), "l"(g) : "memory")
#define CP_COMMIT() asm volatile("cp.async.commit_group;" ::: "memory")
#define CP_WAIT(n)  asm volatile("cp.async.wait_group %0;" :: "n"(n) : "memory")

#define MMA_BF16(d, a0, a1, a2, a3, b0, b1) \
    asm volatile( \
        "mma.sync.aligned.m16n8k16.row.col.f32.bf16.bf16.f32 " \
        "{%0,%1,%2,%3}, {%4,%5,%6,%7}, {%8,%9}, {%0,%1,%2,%3};" \
        : "+f"((d)[0]), "+f"((d)[1]), "+f"((d)[2]), "+f"((d)[3]) \
        : "r"(a0), "r"(a1), "r"(a2), "r"(a3), "r"(b0), "r"(b1))

// TERM-MAJOR order (NI=4): all lo*hi, all hi*lo, all hi*hi across the 8
// (ni x mi) accumulators -> dependent reuse distance 8 issues, hides HMMA
// latency. Per-accumulator term order unchanged -> numerics identical.
#define MMA_BLOCK_TM(ACC, Asb, Bsb, arow, brow, o1, o2)                       \
    {                                                                          \
        uint2 Af[2][4];                                                        \
        _Pragma("unroll")                                                      \
        for (int mi = 0; mi < 2; mi++) {                                       \
            const uint32_t* p = (Asb) + (((arow) + mi * 16) << 5);             \
            Af[mi][0] = *(const uint2*)(p + (o1));                             \
            Af[mi][1] = *(const uint2*)(p + 256 + (o1));                       \
            Af[mi][2] = *(const uint2*)(p + (o2));                             \
            Af[mi][3] = *(const uint2*)(p + 256 + (o2));                       \
        }                                                                      \
        uint2 Bf0[4], Bf1[4];                                                  \
        _Pragma("unroll")                                                      \
        for (int q = 0; q < 4; q++) {                                          \
            const uint32_t* bp = (Bsb) + (((brow) + q * 8) << 5);              \
            Bf0[q] = *(const uint2*)(bp + (o1));                               \
            Bf1[q] = *(const uint2*)(bp + (o2));                               \
        }                                                                      \
        _Pragma("unroll")                                                      \
        for (int q = 0; q < 4; q++)                                            \
            _Pragma("unroll")                                                  \
            for (int mi = 0; mi < 2; mi++)                                     \
                MMA_BF16(ACC[mi][q], Af[mi][0].y, Af[mi][1].y,                 \
                         Af[mi][2].y, Af[mi][3].y, Bf0[q].x, Bf1[q].x);        \
        _Pragma("unroll")                                                      \
        for (int q = 0; q < 4; q++)                                            \
            _Pragma("unroll")                                                  \
            for (int mi = 0; mi < 2; mi++)                                     \
                MMA_BF16(ACC[mi][q], Af[mi][0].x, Af[mi][1].x,                 \
                         Af[mi][2].x, Af[mi][3].x, Bf0[q].y, Bf1[q].y);        \
        _Pragma("unroll")                                                      \
        for (int q = 0; q < 4; q++)                                            \
            _Pragma("unroll")                                                  \
            for (int mi = 0; mi < 2; mi++)                                     \
                MMA_BF16(ACC[mi][q], Af[mi][0].x, Af[mi][1].x,                 \
                         Af[mi][2].x, Af[mi][3].x, Bf0[q].x, Bf1[q].x);        \
    }

// ---------------- bf16x3 mma.sync GEMM, compile-time K ----------------------
// BM=64: PAIR mainloop (2 k-tiles/sync), TERM-MAJOR mma, 4 slots, fully
// unrolled over KT/32 k-tiles -> immediate-offset cp.async addressing.
// C[M, 128-tile of Ng] = epi(A @ B^T + bias).
// AMODE 0: row-major (M,KT). 1: m -> wf[s=m>>2] slice (m&3)+1 (K=128).
// RESID 0: none; 1: packed bf16 hi/lo; 2: fp32 (RBCAST: row m>>2).
template <int KT, int AMODE, bool RELU, int RESID, bool RBCAST, bool BIAS2D,
          bool PERM, bool PACKOUT>
__global__ void __launch_bounds__(256, 2)
mma_gemm(int M, int Ng,
         const uint32_t* __restrict__ A,
         const uint32_t* __restrict__ Bs,
         const float* __restrict__ bias, const void* __restrict__ resid,
         float* __restrict__ C) {
    extern __shared__ uint32_t smu[];
    constexpr int ASIZE = 64 * 32;
    constexpr int SSTRIDE = ASIZE + 4096;
    constexpr int NSTG = 4;
    constexpr int nK = KT >> 5;          // even for all instantiations
    int tid = threadIdx.x;
    int lane = tid & 31, wid = tid >> 5;
    int wm = wid & 1, wn = wid >> 1;
    int m0 = blockIdx.y << 6, n0 = blockIdx.x << 7;
    uint32_t smbase = smem_u32(smu);

    const uint32_t* gA[2];
    uint32_t saA[2];
#pragma unroll
    for (int i = 0; i < 2; i++) {
        int c = tid + (i << 8);
        int row = c >> 3, j = c & 7;
        if (AMODE == 0) {
            gA[i] = A + (size_t)(m0 + row) * KT + (j << 2);
        } else {
            int m = m0 + row;
            gA[i] = A + (size_t)(m >> 2) * 640 + (((m & 3) + 1) << 7) + (j << 2);
        }
        int ch = j ^ ((row & 3) << 1);
        saA[i] = (row << 5) + (ch << 2);
    }
    const uint32_t* gB[4];
    uint32_t saB[4];
#pragma unroll
    for (int i = 0; i < 4; i++) {
        int c = tid + (i << 8);
        int row = c >> 3, j = c & 7;
        gB[i] = Bs + (size_t)(n0 + row) * KT + (j << 2);
        int ch = j ^ ((row & 3) << 1);
        saB[i] = ASIZE + (row << 5) + (ch << 2);
    }

    float acc[2][4][4];
#pragma unroll
    for (int mi = 0; mi < 2; mi++)
#pragma unroll
        for (int ni = 0; ni < 4; ni++)
#pragma unroll
            for (int u = 0; u < 4; u++) acc[mi][ni][u] = 0.f;

    auto load_tile = [&](int kt) {   // kt is compile-time after unroll
        uint32_t st = (kt % NSTG) * SSTRIDE;
#pragma unroll
        for (int i = 0; i < 2; i++)
            CP_ASYNC(smbase + ((st + saA[i]) << 2), gA[i] + kt * 32);
#pragma unroll
        for (int i = 0; i < 4; i++)
            CP_ASYNC(smbase + ((st + saB[i]) << 2), gB[i] + kt * 32);
        CP_COMMIT();
    };

    int g = lane >> 2, kc = lane & 3;
    int swz = (g & 3) << 2;
    int arow = wm * 32 + g;
    int brow = wn * 32 + g;
    int o1v[2], o2v[2];
#pragma unroll
    for (int ks = 0; ks < 2; ks++) {
        o1v[ks] = 2 * ((ks * 8 + kc) ^ swz);
        o2v[ks] = 2 * ((ks * 8 + kc + 4) ^ swz);
    }

    // pair mainloop, fully unrolled: one sync per 2 k-tiles
    load_tile(0);
    load_tile(1);
#pragma unroll
    for (int kt = 0; kt < nK; kt += 2) {
        CP_WAIT(0);
        __syncthreads();
        if (kt + 2 < nK) {
            load_tile(kt + 2);
            load_tile(kt + 3);
        }
#pragma unroll
        for (int half = 0; half < 2; half++) {
            const uint32_t* Asb = smu + ((kt + half) % NSTG) * SSTRIDE;
            const uint32_t* Bsb = Asb + ASIZE;
#pragma unroll
            for (int ks = 0; ks < 2; ks++) {
                MMA_BLOCK_TM(acc, Asb, Bsb, arow, brow, o1v[ks], o2v[ks]);
            }
        }
    }

    // Epilogue. c0:(g,2t) c1:(g,2t+1) c2:(g+8,2t) c3:(g+8,2t+1)
    int mrow = m0 + wm * 32 + g;
    int rsel = mrow & 3;
    int nc0 = n0 + wn * 32 + 2 * kc;
    const uint32_t* Rp = (const uint32_t*)resid;
    const float* Rf = (const float*)resid;
#pragma unroll
    for (int ni = 0; ni < 4; ni++) {
        int n = nc0 + ni * 8;
        int boff = BIAS2D ? rsel * Ng : 0;
        float bv0 = bias[boff + n], bv1 = bias[boff + n + 1];
#pragma unroll
        for (int mi = 0; mi < 2; mi++) {
#pragma unroll
            for (int h2 = 0; h2 < 2; h2++) {
                int m = mrow + mi * 16 + h2 * 8;
                float x0 = acc[mi][ni][2 * h2]     + bv0;
                float x1 = acc[mi][ni][2 * h2 + 1] + bv1;
                if (RESID == 1) {
                    uint2 rv = *(const uint2*)(Rp + (size_t)m * Ng + n);
                    float2 rh = bf2_unpack(rv.x), rl = bf2_unpack(rv.y);
                    x0 += rh.x + rl.x;
                    x1 += rh.y + rl.y;
                } else if (RESID == 2) {
                    size_t rr = RBCAST ? ((size_t)(m >> 2) * Ng + n)
                                       : ((size_t)m * Ng + n);
                    x0 += Rf[rr];
                    x1 += Rf[rr + 1];
                }
                if (RELU) { x0 = fmaxf(x0, 0.f); x1 = fmaxf(x1, 0.f); }
                if (PERM) {
                    int bb = m >> 14;
                    size_t low = (size_t)(m & 16383);
                    C[(((size_t)(bb * 128 + n)) << 14) + low] = x0;
                    C[(((size_t)(bb * 128 + n + 1)) << 14) + low] = x1;
                } else if (PACKOUT) {
                    uint2 pw = pack_hilo(x0, x1);
                    *(uint2*)((uint32_t*)C + (size_t)m * Ng + n) = pw;
                } else {
                    *(float2*)(C + (size_t)m * Ng + n) = make_float2(x0, x1);
                }
            }
        }
    }
}

// ---------------- fused qf2 + Y kernel (BM=64, term-major mma) --------------
__global__ void __launch_bounds__(256, 2)
fused_qf2_y(const uint32_t* __restrict__ qf, const uint32_t* __restrict__ wes,
            const float* __restrict__ b_end, const uint32_t* __restrict__ featT,
            const uint32_t* __restrict__ w1cds, const float* __restrict__ b_mlp1,
            float* __restrict__ Y) {
    extern __shared__ uint32_t smu[];
    uint32_t* Hs = smu;                     // 4 tiles x 2048 u32 = 8192
    const uint32_t PIPE = 8192;             // 3 stages x (A 2048 + B 4096)
    const int SSTRIDE = 6144;
    int tid = threadIdx.x;
    int lane = tid & 31, wid = tid >> 5;
    int wm = wid & 1, wn = wid >> 1;
    int m0 = blockIdx.x << 6;
    uint32_t smbase = smem_u32(smu);

    int g = lane >> 2, kc = lane & 3;
    int swz = (g & 3) << 2;
    int arow = wm * 32 + g;
    int brow = wn * 32 + g;
    int o1v[2], o2v[2];
#pragma unroll
    for (int ks = 0; ks < 2; ks++) {
        o1v[ks] = 2 * ((ks * 8 + kc) ^ swz);
        o2v[ks] = 2 * ((ks * 8 + kc + 4) ^ swz);
    }

    int rowA[2], jA[2];
    uint32_t saA[2];
#pragma unroll
    for (int i = 0; i < 2; i++) {
        int c = tid + (i << 8);
        int row = c >> 3, j = c & 7;
        rowA[i] = row; jA[i] = j;
        int ch = j ^ ((row & 3) << 1);
        saA[i] = (row << 5) + (ch << 2);
    }
    int rowB[4], jB[4];
    uint32_t saB[4];
#pragma unroll
    for (int i = 0; i < 4; i++) {
        int c = tid + (i << 8);
        int row = c >> 3, j = c & 7;
        rowB[i] = row; jB[i] = j;
        int ch = j ^ ((row & 3) << 1);
        saB[i] = 2048 + (row << 5) + (ch << 2);
    }

    // ===== Phase 1: qf2 tile (K=128, 4 k-tiles, 3-stage) =====
    {
        auto load1 = [&](int kt) {
            uint32_t st = PIPE + (kt % 3) * SSTRIDE;
#pragma unroll
            for (int i = 0; i < 2; i++)
                CP_ASYNC(smbase + ((st + saA[i]) << 2),
                         qf + (size_t)(m0 + rowA[i]) * 128 + (kt << 5) + (jA[i] << 2));
#pragma unroll
            for (int i = 0; i < 4; i++)
                CP_ASYNC(smbase + ((st + saB[i]) << 2),
                         wes + (size_t)rowB[i] * 128 + (kt << 5) + (jB[i] << 2));
            CP_COMMIT();
        };
        load1(0);
        load1(1);
        float acc[2][4][4];
#pragma unroll
        for (int mi = 0; mi < 2; mi++)
#pragma unroll
            for (int ni = 0; ni < 4; ni++)
#pragma unroll
                for (int u = 0; u < 4; u++) acc[mi][ni][u] = 0.f;
#pragma unroll
        for (int kt = 0; kt < 4; kt++) {
            if (kt < 3) { CP_WAIT(1); } else { CP_WAIT(0); }
            __syncthreads();
            if (kt + 2 < 4) load1(kt + 2);
            const uint32_t* Asb = smu + PIPE + (kt % 3) * SSTRIDE;
            const uint32_t* Bsb = Asb + 2048;
#pragma unroll
            for (int ks = 0; ks < 2; ks++) {
                MMA_BLOCK_TM(acc, Asb, Bsb, arow, brow, o1v[ks], o2v[ks]);
            }
        }
        int nc0 = wn * 32 + 2 * kc;
#pragma unroll
        for (int ni = 0; ni < 4; ni++) {
            int n = nc0 + ni * 8;
            float bv0 = b_end[n], bv1 = b_end[n + 1];
#pragma unroll
            for (int mi = 0; mi < 2; mi++) {
#pragma unroll
                for (int h2 = 0; h2 < 2; h2++) {
                    int ml = arow + mi * 16 + h2 * 8;
                    uint2 rv = *(const uint2*)(featT + ((size_t)(m0 + ml) << 7) + n);
                    float2 rh = bf2_unpack(rv.x), rl = bf2_unpack(rv.y);
                    float x0 = acc[mi][ni][2 * h2]     + bv0 + rh.x + rl.x;
                    float x1 = acc[mi][ni][2 * h2 + 1] + bv1 + rh.y + rl.y;
                    x0 = fmaxf(x0, 0.f);
                    x1 = fmaxf(x1, 0.f);
                    uint2 pw = pack_hilo(x0, x1);
                    int p = n >> 1;
                    uint32_t off = (uint32_t)(p >> 4) * 2048 + (ml << 5)
                                 + 2 * ((p & 15) ^ ((ml & 3) << 2));
                    *(uint2*)(Hs + off) = pw;
                }
            }
        }
    }

    // ===== Phase 2: Y, two n-passes, K=256 (kt<4 from Hs, kt>=4 featT) =====
#pragma unroll 1
    for (int np = 0; np < 2; np++) {
        __syncthreads();
        const uint32_t* Bb = w1cds + ((size_t)np << 15);
        auto load2 = [&](int kt) {
            uint32_t st = PIPE + (kt % 3) * SSTRIDE;
            if (kt >= 4) {
#pragma unroll
                for (int i = 0; i < 2; i++)
                    CP_ASYNC(smbase + ((st + saA[i]) << 2),
                             featT + ((size_t)(m0 + rowA[i]) << 7) + ((kt - 4) << 5) + (jA[i] << 2));
            }
#pragma unroll
            for (int i = 0; i < 4; i++)
                CP_ASYNC(smbase + ((st + saB[i]) << 2),
                         Bb + (size_t)rowB[i] * 256 + (kt << 5) + (jB[i] << 2));
            CP_COMMIT();
        };
        load2(0);
        load2(1);
        float acc[2][4][4];
#pragma unroll
        for (int mi = 0; mi < 2; mi++)
#pragma unroll
            for (int ni = 0; ni < 4; ni++)
#pragma unroll
                for (int u = 0; u < 4; u++) acc[mi][ni][u] = 0.f;
#pragma unroll
        for (int kt = 0; kt < 8; kt++) {
            if (kt < 7) { CP_WAIT(1); } else { CP_WAIT(0); }
            __syncthreads();
            if (kt + 2 < 8) load2(kt + 2);
            const uint32_t* slot = smu + PIPE + (kt % 3) * SSTRIDE;
            const uint32_t* Asb = (kt < 4) ? (Hs + kt * 2048) : slot;
            const uint32_t* Bsb = slot + 2048;
#pragma unroll
            for (int ks = 0; ks < 2; ks++) {
                MMA_BLOCK_TM(acc, Asb, Bsb, arow, brow, o1v[ks], o2v[ks]);
            }
        }
        int nc0 = (np << 7) + wn * 32 + 2 * kc;
#pragma unroll
        for (int ni = 0; ni < 4; ni++) {
            int n = nc0 + ni * 8;
            float bv0 = b_mlp1[n], bv1 = b_mlp1[n + 1];
#pragma unroll
            for (int mi = 0; mi < 2; mi++) {
#pragma unroll
                for (int h2 = 0; h2 < 2; h2++) {
                    int m = m0 + arow + mi * 16 + h2 * 8;
                    float x0 = acc[mi][ni][2 * h2]     + bv0;
                    float x1 = acc[mi][ni][2 * h2 + 1] + bv1;
                    *(float2*)(Y + ((size_t)m << 8) + n) = make_float2(x0, x1);
                }
            }
        }
    }
}

// -------- kernel-point correlation: packed feat0 -> packed wf --------------
__global__ void kp_wf_kernel(const float* __restrict__ pos,
                             const int* __restrict__ idx,
                             const float* __restrict__ qp,
                             const uint32_t* __restrict__ feat0,
                             uint32_t* __restrict__ wf) {
    int s = blockIdx.x;
    int b = s >> 12, n = s & (BQ_N - 1);
    int c = threadIdx.x;
    __shared__ float wsh[R1][KN];
    __shared__ int nidx[KN];
    if (c < KN) {
        int m = idx[(size_t)s * KN + c];
        nidx[c] = m;
        float wr[R1];
#pragma unroll
        for (int r = 0; r < R1; r++) wr[r] = 0.f;
        if (m < BQ_N) {
            const float* p = pos + (size_t)b * 3 * BQ_N;
            float rx = p[m] - p[n];
            float ry = p[BQ_N + m] - p[BQ_N + n];
            float rz = p[2 * BQ_N + m] - p[2 * BQ_N + n];
#pragma unroll
            for (int r = 0; r < R1; r++) {
                float dx = rx - qp[r];
                float dy = ry - qp[R1 + r];
                float dz = rz - qp[2 * R1 + r];
                float d = sqrtf(dx * dx + dy * dy + dz * dz);
                wr[r] = fmaxf(0.f, 1.f - d / 0.1f);
            }
        }
#pragma unroll
        for (int r = 0; r < R1; r++) wsh[r][c] = wr[r];
    }
    __syncthreads();
    float acc[R1] = {0.f, 0.f, 0.f, 0.f, 0.f};
    bool odd = (c & 1);
    int ce = c & ~1;
#pragma unroll 4
    for (int k = 0; k < KN; k++) {
        int m = nidx[k];
        float f = 0.f;
        if (m < BQ_N) {
            uint2 w = *(const uint2*)(feat0 + (((size_t)(b * BQ_N + m)) << 7) + ce);
            float2 hh = bf2_unpack(w.x), ll = bf2_unpack(w.y);
            f = odd ? (hh.y + ll.y) : (hh.x + ll.x);
        }
#pragma unroll
        for (int r = 0; r < R1; r++) acc[r] += wsh[r][k] * f;
    }
#pragma unroll
    for (int r = 0; r < R1; r++) {
        float v = acc[r];
        float vp = __shfl_xor_sync(0xffffffffu, v, 1);
        if (!odd) {
            uint2 pw = pack_hilo(v, vp);
            *(uint2*)(wf + (size_t)s * 640 + r * 128 + c) = pw;
        }
    }
}

// ---- setup: transpose(+pack) | ballquery | prep, by blockIdx range --------
#define T_BLOCKS 2048
#define B_BLOCKS 2048         // 1 point per warp, direct LDG
#define PREP_TOTAL (8192 + 40960 + 8192 + 16384 + 32768 + 16384 + 1024 + 12)
#define P_BLOCKS ((PREP_TOTAL + 255) / 256)

__global__ void __launch_bounds__(256) setup_kernel(
    const float* __restrict__ feat, const float* __restrict__ pos,
    const float* __restrict__ w_begin, const float* __restrict__ kpw,
    const float* __restrict__ w_end, const float* __restrict__ w1,
    const float* __restrict__ w2, const float* __restrict__ qp,
    uint32_t* __restrict__ featT, int* __restrict__ idx,
    uint32_t* __restrict__ wbs, uint32_t* __restrict__ kpTs,
    uint32_t* __restrict__ wes, uint32_t* __restrict__ w1as,
    uint32_t* __restrict__ w1cds, uint32_t* __restrict__ m2s,
    float* __restrict__ bias2d, float* __restrict__ out12) {
    extern __shared__ float dynf[];
    int bid = blockIdx.x;
    int tid = threadIdx.x;
    if (bid < T_BLOCKS) {
        float (*tile)[33] = (float (*)[33])dynf;
        int b = bid >> 9;
        int n0 = (bid & 127) * 32, c0 = ((bid >> 7) & 3) * 32;
        int tx = tid & 31, ty = tid >> 5;
#pragma unroll
        for (int i = ty; i < 32; i += 8)
            tile[i][tx] = feat[((size_t)(b * CC + c0 + i)) * BQ_N + n0 + tx];
        __syncthreads();
#pragma unroll
        for (int i = ty; i < 32; i += 8) {
            float v = tile[tx][i];
            float vp = __shfl_xor_sync(0xffffffffu, v, 1);
            if (!(tx & 1)) {
                uint2 pw = pack_hilo(v, vp);
                *(uint2*)(featT + (((size_t)(b * BQ_N + n0 + i)) << 7) + c0 + tx) = pw;
            }
        }
        return;
    }
    if (bid < T_BLOCKS + B_BLOCKS) {
        int t = bid - T_BLOCKS;
        int b = t >> 9, bx = t & 511;
        const float* px = pos + (size_t)b * 3 * BQ_N;
        const float* py = px + BQ_N;
        const float* pz = px + 2 * BQ_N;
        int warp = tid >> 5, lane = tid & 31;
        int n = bx * 8 + warp;
        float xn = px[n], yn = py[n], zn = pz[n];
        float nn = xn * xn + yn * yn + zn * zn;
        int* out = idx + (size_t)(b * BQ_N + n) * KN;
        int count = 0;
        for (int m0 = 0; m0 < BQ_N && count < KN; m0 += 32) {
            int m = m0 + lane;
            float xm = px[m], ym = py[m], zm = pz[m];
            float nm = xm * xm + ym * ym + zm * zm;
            float dt = xn * xm + yn * ym + zn * zm;
            float sqd = (nn + nm) - 2.0f * dt;
            bool ok = (sqd <= CONV_R2);
            unsigned msk = __ballot_sync(0xffffffffu, ok);
            int p2 = count + __popc(msk & ((1u << lane) - 1u));
            if (ok && p2 < KN) out[p2] = m;
            count += __popc(msk);
            if (count > KN) count = KN;
        }
        for (int p2 = count + lane; p2 < KN; p2 += 32) out[p2] = BQ_N;
        return;
    }
    int t = (bid - T_BLOCKS - B_BLOCKS) * 256 + tid;
    if (t < 8192) {
        int o = t >> 6, p = t & 63;
        *(uint2*)(wbs + o * 128 + 2 * p) =
            pack_hilo(w_begin[o * 128 + 2 * p], w_begin[o * 128 + 2 * p + 1]);
        return;
    }
    t -= 8192;
    if (t < 40960) {
        int c = t / 320, p = t % 320;
        *(uint2*)(kpTs + (size_t)c * 640 + 2 * p) =
            pack_hilo(kpw[(size_t)(2 * p) * 128 + c], kpw[(size_t)(2 * p + 1) * 128 + c]);
        return;
    }
    t -= 40960;
    if (t < 8192) {
        int o = t >> 6, p = t & 63;
        *(uint2*)(wes + o * 128 + 2 * p) =
            pack_hilo(w_end[o * 128 + 2 * p], w_end[o * 128 + 2 * p + 1]);
        return;
    }
    t -= 8192;
    if (t < 16384) {
        int o = t >> 6, p = t & 63;
        *(uint2*)(w1as + o * 128 + 2 * p) =
            pack_hilo(w1[(size_t)o * 387 + 2 * p], w1[(size_t)o * 387 + 2 * p + 1]);
        return;
    }
    t -= 16384;
    if (t < 32768) {
        int o = t >> 7, p = t & 127;
        *(uint2*)(w1cds + (size_t)o * 256 + 2 * p) =
            pack_hilo(w1[(size_t)o * 387 + 131 + 2 * p], w1[(size_t)o * 387 + 132 + 2 * p]);
        return;
    }
    t -= 32768;
    if (t < 16384) {
        int o = t >> 7, p = t & 127;
        *(uint2*)(m2s + (size_t)o * 256 + 2 * p) =
            pack_hilo(w2[(size_t)o * 256 + 2 * p], w2[(size_t)o * 256 + 2 * p + 1]);
        return;
    }
    t -= 16384;
    if (t < 1024) {
        int r = t >> 8, n = t & 255;
        float s = 0.f;
#pragma unroll
        for (int a = 0; a < 3; a++)
            s += w1[(size_t)n * 387 + 128 + a] * qp[a * R1 + r + 1];
        bias2d[r * 256 + n] = s;
        return;
    }
    t -= 1024;
    if (t >= 0 && t < 12) {
        int a = t >> 2, r = (t & 3) + 1;
        out12[t] = qp[a * R1 + r];
    }
}

// ---------------- launch ----------------------------------------------------
extern "C" void kernel_launch(void* const* d_in, const int* in_sizes, int n_in,
                              void* d_out, int out_size) {
    (void)in_sizes; (void)n_in; (void)out_size;
    const float* pos       = (const float*)d_in[0];
    const float* feat      = (const float*)d_in[1];
    const float* qp        = (const float*)d_in[2];
    const float* w_begin   = (const float*)d_in[3];
    const float* b_begin   = (const float*)d_in[4];
    const float* kp_weight = (const float*)d_in[5];
    const float* kp_bias   = (const float*)d_in[6];
    const float* w_end     = (const float*)d_in[7];
    const float* b_end     = (const float*)d_in[8];
    const float* w_mlp1    = (const float*)d_in[9];
    const float* b_mlp1    = (const float*)d_in[10];
    const float* w_mlp2    = (const float*)d_in[11];
    const float* b_mlp2    = (const float*)d_in[12];
    float* out = (float*)d_out;

    uint32_t *featT, *feat0, *wf, *qf, *h;
    uint32_t *wbs, *kpTs, *wes, *w1as, *w1cds, *m2s;
    float *Y, *bias2d;
    int* idx;
    cudaGetSymbolAddress((void**)&featT, g_featT);
    cudaGetSymbolAddress((void**)&feat0, g_feat0);
    cudaGetSymbolAddress((void**)&idx,   g_idx);
    cudaGetSymbolAddress((void**)&wf,    g_wf);
    cudaGetSymbolAddress((void**)&qf,    g_qf);
    cudaGetSymbolAddress((void**)&Y,     g_Y);
    cudaGetSymbolAddress((void**)&h,     g_h);
    cudaGetSymbolAddress((void**)&wbs,   g_wbs);
    cudaGetSymbolAddress((void**)&kpTs,  g_kpTs);
    cudaGetSymbolAddress((void**)&wes,   g_wes);
    cudaGetSymbolAddress((void**)&w1as,  g_w1as);
    cudaGetSymbolAddress((void**)&w1cds, g_w1cds);
    cudaGetSymbolAddress((void**)&m2s,   g_m2s);
    cudaGetSymbolAddress((void**)&bias2d, g_bias2d);

    const int SMEM_SETUP = 32 * 33 * 4 + 256;
    const int SMEM_S = 4 * (64 * 32 + 4096) * 4;    // 98304 B (BM=64, 4 slots)
    const int SMEM_F = (8192 + 3 * 6144) * 4;       // 106496 B (fused qf2+Y)
    cudaFuncSetAttribute(setup_kernel,
                         cudaFuncAttributeMaxDynamicSharedMemorySize, SMEM_SETUP);
    cudaFuncSetAttribute(fused_qf2_y,
                         cudaFuncAttributeMaxDynamicSharedMemorySize, SMEM_F);
#define SETSM(...) cudaFuncSetAttribute(mma_gemm<__VA_ARGS__>, \
        cudaFuncAttributeMaxDynamicSharedMemorySize, SMEM_S)
    SETSM(128, 0, false, 0, false, false, false, true);
    SETSM(640, 0, true,  0, false, false, false, true);
    SETSM(128, 1, true,  2, true,  true,  false, true);
    SETSM(256, 0, true,  0, false, false, true,  false);
#undef SETSM

    // Stage 0: fused transpose + ball query + prep
    setup_kernel<<<T_BLOCKS + B_BLOCKS + P_BLOCKS, 256, SMEM_SETUP>>>(
        feat, pos, w_begin, kp_weight, w_end, w_mlp1, w_mlp2, qp,
        featT, idx, wbs, kpTs, wes, w1as, w1cds, m2s, bias2d, out);

    // feat0 = featT @ w_begin^T + b_begin          (packed out)
    mma_gemm<128, 0, false, 0, false, false, false, true><<<dim3(1, 256), 256, SMEM_S>>>(
        S_TOT, 128, featT, wbs, b_begin, nullptr, (float*)feat0);

    // kernel-point correlation -> wf (S, 640)      (packed out)
    kp_wf_kernel<<<S_TOT, 128>>>(pos, idx, qp, feat0, wf);

    // qf = relu(wf @ kpT^T + kp_bias)              (packed out)
    mma_gemm<640, 0, true, 0, false, false, false, true><<<dim3(1, 256), 256, SMEM_S>>>(
        S_TOT, 128, wf, kpTs, kp_bias, nullptr, (float*)qf);

    // fused: qf2 (smem only) -> Y = [qf2|featT] @ w1cd^T + b_mlp1
    fused_qf2_y<<<256, 256, SMEM_F>>>(qf, wes, b_end, featT, w1cds, b_mlp1, Y);

    // h = relu(wf_r @ w1a^T + bias2d[r] + Y[s])    (packed out, BM=64)
    mma_gemm<128, 1, true, 2, true, true, false, true><<<dim3(2, 1024), 256, SMEM_S>>>(
        S2_TOT, 256, wf, w1as, bias2d, Y, (float*)h);

    // queries = relu(h @ w_mlp2^T + b_mlp2), PERM scatter (BM=64)
    mma_gemm<256, 0, true, 0, false, false, true, false><<<dim3(1, 1024), 256, SMEM_S>>>(
        S2_TOT, 128, h, m2s, b_mlp2, nullptr, out + 12);
}